// round 5
// baseline (speedup 1.0000x reference)
#include <cuda_runtime.h>
#include <cuda_bf16.h>
#include <stdint.h>

#define N_AGENTS 16384
#define OBS_DIM  2048
#define HID      512

// ---- int8 IMMA GEMM tiling ----
#define BM 128
#define BN 128
#define KC 128                   // int8 K per chunk (128B rows)
#define NCHUNK (OBS_DIM / KC)    // 16
#define NTILES (HID / BN)        // 4
#define MTILES (N_AGENTS / BM)   // 128

#define SA_H 0
#define SA_L 16384
#define SB_H 32768
#define SB_L 49152
#define STAGE 65536              // A(h+l 32K) + B(h+l 32K)
#define NSTAGE 3
#define SMEM_TOTAL (NSTAGE * STAGE + 512)   // 197120

// weights for the 3-term recombination: 2^-28 * {16384, 128}
#define W_HH 6.103515625e-05f
#define W_X  4.76837158203125e-07f

__device__ float g_hidden[(size_t)N_AGENTS * HID];
// pre-quantized, pre-swizzled tiles: [tile][chunk][h 16K | l 16K]
__device__ __align__(1024) unsigned char g_Bstage[(size_t)NTILES * NCHUNK * 32768];
__device__ __align__(1024) unsigned char g_Astage[(size_t)MTILES * NCHUNK * 32768];

static __device__ __forceinline__ uint32_t smem_addr_u32(const void* p) {
    uint32_t a;
    asm("{ .reg .u64 t; cvta.to.shared.u64 t, %1; cvt.u32.u64 %0, t; }" : "=r"(a) : "l"(p));
    return a;
}

static __device__ __forceinline__ void ldm_x4(uint32_t* r, uint32_t addr) {
    asm volatile("ldmatrix.sync.aligned.m8n8.x4.shared.b16 {%0,%1,%2,%3}, [%4];"
                 : "=r"(r[0]), "=r"(r[1]), "=r"(r[2]), "=r"(r[3]) : "r"(addr));
}

static __device__ __forceinline__ void mma_s8(int* c, const uint32_t* a,
                                              const uint32_t* b) {
    asm volatile(
        "mma.sync.aligned.m16n8k32.row.col.s32.s8.s8.s32 "
        "{%0,%1,%2,%3}, {%4,%5,%6,%7}, {%8,%9}, {%0,%1,%2,%3};"
        : "+r"(c[0]), "+r"(c[1]), "+r"(c[2]), "+r"(c[3])
        : "r"(a[0]), "r"(a[1]), "r"(a[2]), "r"(a[3]), "r"(b[0]), "r"(b[1]));
}

// ---------------------------------------------------------------------------
// Pre-quantize: fp32 [rows x 2048] -> pre-swizzled h/l int8 tile staging.
// q = clamp(round(x*scale), +-16255); h = (q+64)>>7 (in [-127,127]);
// l = q - 128h (in [-64,63]). Tile = 128 rows x 128 k (h 16KB | l 16KB).
// ---------------------------------------------------------------------------
__global__ void conv_i8_kernel(const float* __restrict__ S, unsigned char* __restrict__ D,
                               float scale) {
    const int gid = blockIdx.x * 256 + threadIdx.x;
    const int n   = gid >> 7;                  // row
    const int k0  = (gid & 127) << 4;          // 16-element column offset
    const float4* src = (const float4*)(S + (size_t)n * OBS_DIM + k0);

    uint32_t hw[4], lw[4];
#pragma unroll
    for (int j = 0; j < 4; j++) {
        float4 v = src[j];
        float f[4] = {v.x, v.y, v.z, v.w};
        uint32_t hword = 0, lword = 0;
#pragma unroll
        for (int e = 0; e < 4; e++) {
            int q = __float2int_rn(f[e] * scale);
            q = max(-16255, min(16255, q));
            int h = (q + 64) >> 7;
            int l = q - (h << 7);
            hword |= ((uint32_t)(h & 0xff)) << (8 * e);
            lword |= ((uint32_t)(l & 0xff)) << (8 * e);
        }
        hw[j] = hword; lw[j] = lword;
    }

    const int c  = k0 >> 7;                    // chunk
    const int kl = k0 & 127;                   // byte offset within row
    const int t  = n >> 7;                     // tile
    const int nl = n & 127;                    // row within tile
    const uint32_t byte = (uint32_t)nl * 128 +
                          ((uint32_t)kl ^ ((uint32_t)(nl & 7) << 4));
    unsigned char* blk = D + ((size_t)(t * NCHUNK + c)) * 32768;
    *(uint4*)(blk + byte)         = make_uint4(hw[0], hw[1], hw[2], hw[3]);
    *(uint4*)(blk + 16384 + byte) = make_uint4(lw[0], lw[1], lw[2], lw[3]);
}

// ---------------------------------------------------------------------------
// IMMA GEMM: g_hidden = relu(x @ W_enc^T + b_enc)
// 3-term int8 split (hh@16384, hl+lh@128); 3-stage cp.async ring.
// ---------------------------------------------------------------------------
__global__ __launch_bounds__(256, 1) void enc_gemm_imma(const float* __restrict__ bias) {
    extern __shared__ __align__(1024) unsigned char smem[];
    const int tid = threadIdx.x;
    const int w = tid >> 5, l = tid & 31;
    const int mtile = blockIdx.x >> 2;
    const int ntile = blockIdx.x & 3;
    const int m0 = mtile * BM;
    const int n0 = ntile * BN;
    const uint32_t sb = smem_addr_u32(smem);
    float* bsm = (float*)(smem + NSTAGE * STAGE);
    if (tid < 128) bsm[tid] = bias[n0 + tid];

    const unsigned char* gA = g_Astage + (size_t)mtile * NCHUNK * 32768;
    const unsigned char* gB = g_Bstage + (size_t)ntile * NCHUNK * 32768;

    int acc_hh[4][4][4];
    int acc_x[4][4][4];
#pragma unroll
    for (int i = 0; i < 4; i++)
#pragma unroll
        for (int j = 0; j < 4; j++)
#pragma unroll
            for (int q = 0; q < 4; q++) { acc_hh[i][j][q] = 0; acc_x[i][j][q] = 0; }

    const int wm = (w >> 2) * 64;
    const int wn = (w & 3) * 32;
    const int idx = l & 7, seg = l >> 3;
    const int arl = idx + (seg & 1) * 8;       // A row within m16 tile
    const int acb = (seg >> 1) * 16;           // A k-byte sub-offset
    const int brl = idx + (seg >> 1) * 8;      // B row within n16 group
    const int bkb = (seg & 1) * 16;            // B k-byte sub-offset
    const uint32_t sxor = (uint32_t)idx << 4;  // SW128 reduces to this XOR

#define ISSUE(c, slot)                                                         \
    {                                                                          \
        const uint32_t dst = sb + (slot) * STAGE;                              \
        const unsigned char* ga = gA + (size_t)(c) * 32768;                    \
        const unsigned char* gb = gB + (size_t)(c) * 32768;                    \
        _Pragma("unroll") for (int i = 0; i < 8; i++) {                        \
            uint32_t off = (uint32_t)(i * 256 + tid) * 16;                     \
            asm volatile("cp.async.cg.shared.global [%0], [%1], 16;"           \
                         :: "r"(dst + off), "l"(ga + off) : "memory");         \
        }                                                                      \
        _Pragma("unroll") for (int i = 0; i < 8; i++) {                        \
            uint32_t off = (uint32_t)(i * 256 + tid) * 16;                     \
            asm volatile("cp.async.cg.shared.global [%0], [%1], 16;"           \
                         :: "r"(dst + SB_H + off), "l"(gb + off) : "memory");  \
        }                                                                      \
        asm volatile("cp.async.commit_group;" ::: "memory");                   \
    }

    ISSUE(0, 0);
    ISSUE(1, 1);

    int slot = 0;
    for (int c = 0; c < NCHUNK; c++) {
        if (c + 2 < NCHUNK) {
            asm volatile("cp.async.wait_group 1;" ::: "memory");
        } else {
            asm volatile("cp.async.wait_group 0;" ::: "memory");
        }
        __syncthreads();

        if (c + 2 < NCHUNK) {
            const int ns = (slot + 2 >= NSTAGE) ? slot + 2 - NSTAGE : slot + 2;
            ISSUE(c + 2, ns);
        }

        const uint32_t stA_h = sb + slot * STAGE + SA_H;
        const uint32_t stA_l = sb + slot * STAGE + SA_L;
        const uint32_t stB_h = sb + slot * STAGE + SB_H;
        const uint32_t stB_l = sb + slot * STAGE + SB_L;

#pragma unroll
        for (int ks = 0; ks < 4; ks++) {
            const int kb = ks * 32;
            uint32_t ah[4][4], al[4][4], bh[8], bl[8];
#pragma unroll
            for (int mt = 0; mt < 4; mt++) {
                uint32_t off = (uint32_t)(wm + mt * 16 + arl) * 128 +
                               (((uint32_t)(kb + acb)) ^ sxor);
                ldm_x4(ah[mt], stA_h + off);
                ldm_x4(al[mt], stA_l + off);
            }
#pragma unroll
            for (int g = 0; g < 2; g++) {
                uint32_t off = (uint32_t)(wn + g * 16 + brl) * 128 +
                               (((uint32_t)(kb + bkb)) ^ sxor);
                ldm_x4(&bh[g * 4], stB_h + off);
                ldm_x4(&bl[g * 4], stB_l + off);
            }
#pragma unroll
            for (int mt = 0; mt < 4; mt++)
#pragma unroll
                for (int nt = 0; nt < 4; nt++) {
                    mma_s8(acc_hh[mt][nt], ah[mt], &bh[nt * 2]);
                    mma_s8(acc_x[mt][nt], ah[mt], &bl[nt * 2]);
                    mma_s8(acc_x[mt][nt], al[mt], &bh[nt * 2]);
                }
        }

        slot = (slot + 1 >= NSTAGE) ? 0 : slot + 1;
    }

    // epilogue: recombine, bias, relu, store
#pragma unroll
    for (int mt = 0; mt < 4; mt++)
#pragma unroll
        for (int nt = 0; nt < 4; nt++) {
            const int colL = wn + nt * 8 + (l & 3) * 2;
            const float b0 = bsm[colL], b1 = bsm[colL + 1];
            const int row = m0 + wm + mt * 16 + (l >> 2);
            const int* hh = acc_hh[mt][nt];
            const int* xx = acc_x[mt][nt];
            float2 o0, o1;
            o0.x = fmaxf(fmaf((float)hh[0], W_HH, (float)xx[0] * W_X) + b0, 0.f);
            o0.y = fmaxf(fmaf((float)hh[1], W_HH, (float)xx[1] * W_X) + b1, 0.f);
            o1.x = fmaxf(fmaf((float)hh[2], W_HH, (float)xx[2] * W_X) + b0, 0.f);
            o1.y = fmaxf(fmaf((float)hh[3], W_HH, (float)xx[3] * W_X) + b1, 0.f);
            *(float2*)(g_hidden + (size_t)row * HID + n0 + colL) = o0;
            *(float2*)(g_hidden + (size_t)(row + 8) * HID + n0 + colL) = o1;
        }
}

// ---------------------------------------------------------------------------
// Heads: one warp per 2 agents; Ws/Wc staged in smem
// ---------------------------------------------------------------------------
#define RED_OFF 0
#define WS_OFF  33792                   // 8*32*33*4
#define WC_OFF  (WS_OFF + 32 * 512 * 4)
#define HEAD_SMEM (WC_OFF + 512 * 4)    // 101376 B

__global__ __launch_bounds__(256) void head_kernel(
    const float* __restrict__ Ws, const float* __restrict__ bs,
    const float* __restrict__ Wc, const float* __restrict__ bc,
    const int* __restrict__ skill, const int* __restrict__ action,
    float* __restrict__ out)
{
    extern __shared__ __align__(16) unsigned char hsm[];
    float* red  = (float*)(hsm + RED_OFF);   // [8][32][33]
    float* ws_s = (float*)(hsm + WS_OFF);    // [32][512]
    float* wc_s = (float*)(hsm + WC_OFF);    // [512]

    const int tid = threadIdx.x;
#pragma unroll
    for (int i = 0; i < 16; i++)
        ((float4*)ws_s)[i * 256 + tid] = ((const float4*)Ws)[i * 256 + tid];
    if (tid < 128) ((float4*)wc_s)[tid] = ((const float4*)Wc)[tid];
    __syncthreads();

    const int lane = tid & 31;
    const int w    = tid >> 5;
    const int a0   = (blockIdx.x * 8 + w) * 2;

    const float* h0 = g_hidden + (size_t)a0 * HID;

    float acc[2][33];
#pragma unroll
    for (int s = 0; s < 2; s++)
#pragma unroll
        for (int i = 0; i < 33; i++) acc[s][i] = 0.f;

#pragma unroll 4
    for (int j = 0; j < HID / 32; j++) {
        const int k = j * 32 + lane;
        const float hv0 = h0[k];
        const float hv1 = h0[HID + k];
#pragma unroll
        for (int t = 0; t < 32; t++) {
            const float wv = ws_s[t * HID + k];
            acc[0][t] += hv0 * wv;
            acc[1][t] += hv1 * wv;
        }
        const float wc = wc_s[k];
        acc[0][32] += hv0 * wc;
        acc[1][32] += hv1 * wc;
    }

    const float bsl = bs[lane];
    const float bcv = bc[0];
    float* redw = red + w * 32 * 33;

#pragma unroll
    for (int s = 0; s < 2; s++) {
        const int agent = a0 + s;

        float v = acc[s][32];
#pragma unroll
        for (int o = 16; o > 0; o >>= 1) v += __shfl_xor_sync(0xffffffffu, v, o);

#pragma unroll
        for (int t = 0; t < 32; t++) redw[lane * 33 + t] = acc[s][t];
        __syncwarp();
        float logit = 0.f;
#pragma unroll
        for (int q = 0; q < 32; q++) logit += redw[q * 33 + lane];
        __syncwarp();
        logit += bsl;

        float mx = logit;
#pragma unroll
        for (int o = 16; o > 0; o >>= 1) mx = fmaxf(mx, __shfl_xor_sync(0xffffffffu, mx, o));
        const float e = expf(logit - mx);
        float se = e;
#pragma unroll
        for (int o = 16; o > 0; o >>= 1) se += __shfl_xor_sync(0xffffffffu, se, o);
        const float lse = mx + logf(se);
        const float lsm = logit - lse;
        float ent = -(e / se) * lsm;
#pragma unroll
        for (int o = 16; o > 0; o >>= 1) ent += __shfl_xor_sync(0xffffffffu, ent, o);

        const int act = action[agent];
        const float slp = __shfl_sync(0xffffffffu, lsm, act & 31);

        if (lane == 0) {
            out[0 * N_AGENTS + agent] = (float)act;
            out[1 * N_AGENTS + agent] = (float)skill[agent];
            out[2 * N_AGENTS + agent] = -2.7725887222397811f;  // -ln(16)
            out[3 * N_AGENTS + agent] = slp;
            out[4 * N_AGENTS + agent] = ent;
            out[5 * N_AGENTS + agent] = v + bcv;
        }
    }
}

// ---------------------------------------------------------------------------
// launch
// ---------------------------------------------------------------------------
extern "C" void kernel_launch(void* const* d_in, const int* in_sizes, int n_in,
                              void* d_out, int out_size) {
    (void)in_sizes; (void)n_in; (void)out_size;
    const float* x     = (const float*)d_in[0];
    const float* W_enc = (const float*)d_in[1];
    const float* b_enc = (const float*)d_in[2];
    // d_in[3]=Wm, d_in[4]=bm : dead (selections never returned)
    const float* Ws    = (const float*)d_in[5];
    const float* bs    = (const float*)d_in[6];
    const float* Wc    = (const float*)d_in[7];
    const float* bc    = (const float*)d_in[8];
    const int*   skill = (const int*)d_in[9];
    const int*   act   = (const int*)d_in[10];
    float* out = (float*)d_out;

    unsigned char* dA;
    cudaGetSymbolAddress((void**)&dA, g_Astage);
    unsigned char* dB;
    cudaGetSymbolAddress((void**)&dB, g_Bstage);

    static int cfg_done = 0;
    if (!cfg_done) {
        cudaFuncSetAttribute(enc_gemm_imma, cudaFuncAttributeMaxDynamicSharedMemorySize,
                             SMEM_TOTAL);
        cudaFuncSetAttribute(head_kernel, cudaFuncAttributeMaxDynamicSharedMemorySize,
                             HEAD_SMEM);
        cfg_done = 1;
    }

    conv_i8_kernel<<<256, 256>>>(W_enc, dB, 131072.0f);     // 512 rows, delta = 2^-17
    conv_i8_kernel<<<8192, 256>>>(x, dA, 2048.0f);          // 16384 rows, delta = 2^-11

    enc_gemm_imma<<<NTILES * MTILES, 256, SMEM_TOTAL>>>(b_enc);

    head_kernel<<<N_AGENTS / 16, 256, HEAD_SMEM>>>(Ws, bs, Wc, bc, skill, act, out);
}

// round 6
// speedup vs baseline: 2.7692x; 2.7692x over previous
#include <cuda_runtime.h>
#include <cuda_bf16.h>
#include <stdint.h>

#define N_AGENTS 16384
#define OBS_DIM  2048
#define HID      512

// ---- enc GEMM tiling (bf16 hi/lo 3-term, proven R4 config) ----
#define BM 128
#define BN 128
#define KC 64                    // bf16 K per chunk (128B rows)
#define NCHUNK (OBS_DIM / KC)    // 32
#define NTILES (HID / BN)        // 4
#define MTILES (N_AGENTS / BM)   // 128

#define SA_HI 0
#define SA_LO 16384
#define SB_HI 32768
#define SB_LO 49152
#define STAGE 65536
#define NSTAGE 3
#define SMEM_TOTAL (NSTAGE * STAGE + 512)   // 197120

// pre-converted, pre-swizzled W_enc / x tiles: [tile][chunk][hi 16K | lo 16K]
__device__ __align__(1024) unsigned char g_Bstage[(size_t)NTILES * NCHUNK * 32768];
__device__ __align__(1024) unsigned char g_Astage[(size_t)MTILES * NCHUNK * 32768];
// hidden, written by enc epilogue as pre-swizzled hi/lo bf16 head tiles:
// [mtile][hchunk 0..7][hi 16K | lo 16K]  (hchunk = 64 hidden cols)
__device__ __align__(1024) unsigned char g_Ahead[(size_t)MTILES * 8 * 32768];

static __device__ __forceinline__ uint32_t smem_addr_u32(const void* p) {
    uint32_t a;
    asm("{ .reg .u64 t; cvta.to.shared.u64 t, %1; cvt.u32.u64 %0, t; }" : "=r"(a) : "l"(p));
    return a;
}

static __device__ __forceinline__ void ldm_x4(uint32_t* r, uint32_t addr) {
    asm volatile("ldmatrix.sync.aligned.m8n8.x4.shared.b16 {%0,%1,%2,%3}, [%4];"
                 : "=r"(r[0]), "=r"(r[1]), "=r"(r[2]), "=r"(r[3]) : "r"(addr));
}

static __device__ __forceinline__ void mma_bf16(float* c, const uint32_t* a,
                                                const uint32_t* b) {
    asm volatile(
        "mma.sync.aligned.m16n8k16.row.col.f32.bf16.bf16.f32 "
        "{%0,%1,%2,%3}, {%4,%5,%6,%7}, {%8,%9}, {%0,%1,%2,%3};"
        : "+f"(c[0]), "+f"(c[1]), "+f"(c[2]), "+f"(c[3])
        : "r"(a[0]), "r"(a[1]), "r"(a[2]), "r"(a[3]), "r"(b[0]), "r"(b[1]));
}

static __device__ __forceinline__ void split2(float x0, float x1, uint32_t& hi, uint32_t& lo) {
    __nv_bfloat16 h0 = __float2bfloat16(x0);
    __nv_bfloat16 h1 = __float2bfloat16(x1);
    __nv_bfloat16 l0 = __float2bfloat16(x0 - __bfloat162float(h0));
    __nv_bfloat16 l1 = __float2bfloat16(x1 - __bfloat162float(h1));
    __nv_bfloat162 hp; hp.x = h0; hp.y = h1;
    __nv_bfloat162 lp; lp.x = l0; lp.y = l1;
    hi = *(uint32_t*)&hp;
    lo = *(uint32_t*)&lp;
}

// ---------------------------------------------------------------------------
// Pre-convert: fp32 [rows x 2048] -> pre-swizzled hi/lo bf16 tile staging.
// Tile = 128 rows x 64 k (hi 16KB | lo 16KB).
// ---------------------------------------------------------------------------
__global__ void conv_kernel(const float* __restrict__ S, unsigned char* __restrict__ D) {
    const int gid = blockIdx.x * 256 + threadIdx.x;
    const int n   = gid >> 8;
    const int k0  = (gid & 255) << 3;
    const float* src = S + (size_t)n * OBS_DIM + k0;
    float4 v0 = *(const float4*)src;
    float4 v1 = *(const float4*)(src + 4);
    float f[8] = {v0.x, v0.y, v0.z, v0.w, v1.x, v1.y, v1.z, v1.w};

    uint32_t hi[4], lo[4];
#pragma unroll
    for (int j = 0; j < 4; j++) split2(f[2 * j], f[2 * j + 1], hi[j], lo[j]);

    const int c  = k0 >> 6;
    const int kl = k0 & 63;
    const int t  = n >> 7;
    const int nl = n & 127;
    const uint32_t byte = (uint32_t)nl * 128 +
                          (((uint32_t)kl * 2) ^ ((uint32_t)(nl & 7) << 4));
    unsigned char* blk = D + ((size_t)(t * NCHUNK + c)) * 32768;
    *(uint4*)(blk + byte)         = make_uint4(hi[0], hi[1], hi[2], hi[3]);
    *(uint4*)(blk + 16384 + byte) = make_uint4(lo[0], lo[1], lo[2], lo[3]);
}

// ---------------------------------------------------------------------------
// HMMA GEMM (R4-proven): relu(x @ W_enc^T + b_enc) -> g_Ahead (bf16 hi/lo tiles)
// ---------------------------------------------------------------------------
__global__ __launch_bounds__(256, 1) void enc_gemm_mma(const float* __restrict__ bias) {
    extern __shared__ __align__(1024) unsigned char smem[];
    const int tid = threadIdx.x;
    const int w = tid >> 5, l = tid & 31;
    const int mtile = blockIdx.x >> 2;
    const int ntile = blockIdx.x & 3;
    const int n0 = ntile * BN;
    const uint32_t sb = smem_addr_u32(smem);
    float* bsm = (float*)(smem + NSTAGE * STAGE);
    if (tid < 128) bsm[tid] = bias[n0 + tid];

    const unsigned char* gA = g_Astage + (size_t)mtile * NCHUNK * 32768;
    const unsigned char* gB = g_Bstage + (size_t)ntile * NCHUNK * 32768;

    float acc[4][4][4];
#pragma unroll
    for (int i = 0; i < 4; i++)
#pragma unroll
        for (int j = 0; j < 4; j++)
#pragma unroll
            for (int q = 0; q < 4; q++) acc[i][j][q] = 0.f;

    const int wm = (w >> 2) * 64;
    const int wn = (w & 3) * 32;
    const int idx = l & 7, seg = l >> 3;
    const int arl = idx + (seg & 1) * 8;
    const int acb = (seg >> 1) * 16;
    const int brl = idx + (seg >> 1) * 8;
    const int bkb = (seg & 1) * 16;
    const uint32_t sxor = (uint32_t)idx << 4;

#define ISSUE(c, slot)                                                         \
    {                                                                          \
        const uint32_t dst = sb + (slot) * STAGE;                              \
        const unsigned char* ga = gA + (size_t)(c) * 32768;                    \
        const unsigned char* gb = gB + (size_t)(c) * 32768;                    \
        _Pragma("unroll") for (int i = 0; i < 8; i++) {                        \
            uint32_t off = (uint32_t)(i * 256 + tid) * 16;                     \
            asm volatile("cp.async.cg.shared.global [%0], [%1], 16;"           \
                         :: "r"(dst + off), "l"(ga + off) : "memory");         \
        }                                                                      \
        _Pragma("unroll") for (int i = 0; i < 8; i++) {                        \
            uint32_t off = (uint32_t)(i * 256 + tid) * 16;                     \
            asm volatile("cp.async.cg.shared.global [%0], [%1], 16;"           \
                         :: "r"(dst + SB_HI + off), "l"(gb + off) : "memory"); \
        }                                                                      \
        asm volatile("cp.async.commit_group;" ::: "memory");                   \
    }

    ISSUE(0, 0);
    ISSUE(1, 1);

    int slot = 0;
    for (int c = 0; c < NCHUNK; c++) {
        if (c + 2 < NCHUNK) {
            asm volatile("cp.async.wait_group 1;" ::: "memory");
        } else {
            asm volatile("cp.async.wait_group 0;" ::: "memory");
        }
        __syncthreads();

        if (c + 2 < NCHUNK) {
            const int ns = (slot + 2 >= NSTAGE) ? slot + 2 - NSTAGE : slot + 2;
            ISSUE(c + 2, ns);
        }

        const uint32_t stA_hi = sb + slot * STAGE + SA_HI;
        const uint32_t stA_lo = sb + slot * STAGE + SA_LO;
        const uint32_t stB_hi = sb + slot * STAGE + SB_HI;
        const uint32_t stB_lo = sb + slot * STAGE + SB_LO;

#pragma unroll
        for (int ks = 0; ks < 4; ks++) {
            const int kb = ks * 32;
            uint32_t ah[4][4], al[4][4], bh[8], bl[8];
#pragma unroll
            for (int mt = 0; mt < 4; mt++) {
                uint32_t off = (uint32_t)(wm + mt * 16 + arl) * 128 +
                               (((uint32_t)(kb + acb)) ^ sxor);
                ldm_x4(ah[mt], stA_hi + off);
                ldm_x4(al[mt], stA_lo + off);
            }
#pragma unroll
            for (int g = 0; g < 2; g++) {
                uint32_t off = (uint32_t)(wn + g * 16 + brl) * 128 +
                               (((uint32_t)(kb + bkb)) ^ sxor);
                ldm_x4(&bh[g * 4], stB_hi + off);
                ldm_x4(&bl[g * 4], stB_lo + off);
            }
#pragma unroll
            for (int mt = 0; mt < 4; mt++)
#pragma unroll
                for (int nt = 0; nt < 4; nt++) {
                    mma_bf16(acc[mt][nt], ah[mt], &bh[nt * 2]);
                    mma_bf16(acc[mt][nt], ah[mt], &bl[nt * 2]);
                    mma_bf16(acc[mt][nt], al[mt], &bh[nt * 2]);
                }
        }

        slot = (slot + 1 >= NSTAGE) ? 0 : slot + 1;
    }

    // epilogue: bias + relu, write as pre-swizzled hi/lo bf16 head tiles
    unsigned char* gAh = g_Ahead + (size_t)mtile * 8 * 32768;
#pragma unroll
    for (int mt = 0; mt < 4; mt++)
#pragma unroll
        for (int nt = 0; nt < 4; nt++) {
            const int colL = wn + nt * 8 + (l & 3) * 2;
            const float b0 = bsm[colL], b1 = bsm[colL + 1];
            const int rloc = wm + mt * 16 + (l >> 2);
            const int n = n0 + colL;           // global hidden col
            const int cch = n >> 6;            // head chunk
            const int kc = n & 63;
            unsigned char* blk = gAh + (size_t)cch * 32768;

            float v0x = fmaxf(acc[mt][nt][0] + b0, 0.f);
            float v0y = fmaxf(acc[mt][nt][1] + b1, 0.f);
            float v1x = fmaxf(acc[mt][nt][2] + b0, 0.f);
            float v1y = fmaxf(acc[mt][nt][3] + b1, 0.f);

            uint32_t h01, l01, h23, l23;
            split2(v0x, v0y, h01, l01);
            split2(v1x, v1y, h23, l23);

            const uint32_t by0 = (uint32_t)rloc * 128 +
                                 (((uint32_t)(2 * kc)) ^ ((uint32_t)(rloc & 7) << 4));
            const int r1 = rloc + 8;
            const uint32_t by1 = (uint32_t)r1 * 128 +
                                 (((uint32_t)(2 * kc)) ^ ((uint32_t)(r1 & 7) << 4));
            *(uint32_t*)(blk + by0)         = h01;
            *(uint32_t*)(blk + 16384 + by0) = l01;
            *(uint32_t*)(blk + by1)         = h23;
            *(uint32_t*)(blk + 16384 + by1) = l23;
        }
}

// ---------------------------------------------------------------------------
// Head: per mtile, HMMA [128 x 64 x 512] of hidden vs W'=[Ws;Wc;0pad],
// then per-agent serial softmax/entropy/value. 3-term bf16 hi/lo.
// ---------------------------------------------------------------------------
#define HB_H 0                     // W' hi: 8 chunks x 8KB
#define HB_L 65536                 // W' lo: 8 chunks x 8KB
#define HA   131072                // A ring: 2 x 32KB (reused for logits after)
#define HSTAGE 32768
#define HEAD_SMEM (HA + 2 * HSTAGE)  // 196608

__global__ __launch_bounds__(256, 1) void head_gemm_kernel(
    const float* __restrict__ Ws, const float* __restrict__ bs,
    const float* __restrict__ Wc, const float* __restrict__ bc,
    const int* __restrict__ skill, const int* __restrict__ action,
    float* __restrict__ out)
{
    extern __shared__ __align__(1024) unsigned char smem[];
    const int tid = threadIdx.x;
    const int w = tid >> 5, l = tid & 31;
    const int mtile = blockIdx.x;
    const uint32_t sb = smem_addr_u32(smem);

    // ---- build W' tile: rows 0-31 = Ws, row 32 = Wc, rows 33-63 = 0 ----
#pragma unroll
    for (int it = 0; it < 16; it++) {
        const int u = it * 256 + tid;          // 4096 units: 64 rows x (512/8)
        const int row = u >> 6;
        const int k0 = (u & 63) << 3;
        float f[8];
        if (row < 32) {
            const float4* s4 = (const float4*)(Ws + (size_t)row * HID + k0);
            *(float4*)(f) = s4[0];
            *(float4*)(f + 4) = s4[1];
        } else if (row == 32) {
            const float4* s4 = (const float4*)(Wc + k0);
            *(float4*)(f) = s4[0];
            *(float4*)(f + 4) = s4[1];
        } else {
#pragma unroll
            for (int e = 0; e < 8; e++) f[e] = 0.f;
        }
        uint32_t hi[4], lo[4];
#pragma unroll
        for (int j = 0; j < 4; j++) split2(f[2 * j], f[2 * j + 1], hi[j], lo[j]);
        const int c = k0 >> 6;
        const int kl = k0 & 63;
        const uint32_t byte = (uint32_t)row * 128 +
                              (((uint32_t)kl * 2) ^ ((uint32_t)(row & 7) << 4));
        *(uint4*)(smem + HB_H + c * 8192 + byte) = make_uint4(hi[0], hi[1], hi[2], hi[3]);
        *(uint4*)(smem + HB_L + c * 8192 + byte) = make_uint4(lo[0], lo[1], lo[2], lo[3]);
    }

    const unsigned char* gA = g_Ahead + (size_t)mtile * 8 * 32768;

    float acc[2][4][4];
#pragma unroll
    for (int i = 0; i < 2; i++)
#pragma unroll
        for (int j = 0; j < 4; j++)
#pragma unroll
            for (int q = 0; q < 4; q++) acc[i][j][q] = 0.f;

    const int wm = (w >> 1) * 32;
    const int wn = (w & 1) * 32;
    const int idx = l & 7, seg = l >> 3;
    const int arl = idx + (seg & 1) * 8;
    const int acb = (seg >> 1) * 16;
    const int brl = idx + (seg >> 1) * 8;
    const int bkb = (seg & 1) * 16;
    const uint32_t sxor = (uint32_t)idx << 4;

#define HISSUE(c, slot)                                                        \
    {                                                                          \
        const uint32_t dst = sb + HA + (slot) * HSTAGE;                        \
        const unsigned char* ga = gA + (size_t)(c) * 32768;                    \
        _Pragma("unroll") for (int i = 0; i < 8; i++) {                        \
            uint32_t off = (uint32_t)(i * 256 + tid) * 16;                     \
            asm volatile("cp.async.cg.shared.global [%0], [%1], 16;"           \
                         :: "r"(dst + off), "l"(ga + off) : "memory");         \
        }                                                                      \
        asm volatile("cp.async.commit_group;" ::: "memory");                   \
    }

    HISSUE(0, 0);
    HISSUE(1, 1);
    __syncthreads();   // W' tile ready (also covers first waits)

    for (int c = 0; c < 8; c++) {
        const int slot = c & 1;
        if (c < 6) {
            asm volatile("cp.async.wait_group 1;" ::: "memory");
        } else {
            asm volatile("cp.async.wait_group 0;" ::: "memory");
        }
        __syncthreads();

        const uint32_t stA_hi = sb + HA + slot * HSTAGE;
        const uint32_t stA_lo = stA_hi + 16384;
        const uint32_t stB_hi = sb + HB_H + c * 8192;
        const uint32_t stB_lo = sb + HB_L + c * 8192;

#pragma unroll
        for (int ks = 0; ks < 4; ks++) {
            const int kb = ks * 32;
            uint32_t ah[2][4], al[2][4], bh[8], bl[8];
#pragma unroll
            for (int mt = 0; mt < 2; mt++) {
                uint32_t off = (uint32_t)(wm + mt * 16 + arl) * 128 +
                               (((uint32_t)(kb + acb)) ^ sxor);
                ldm_x4(ah[mt], stA_hi + off);
                ldm_x4(al[mt], stA_lo + off);
            }
#pragma unroll
            for (int g = 0; g < 2; g++) {
                uint32_t off = (uint32_t)(wn + g * 16 + brl) * 128 +
                               (((uint32_t)(kb + bkb)) ^ sxor);
                ldm_x4(&bh[g * 4], stB_hi + off);
                ldm_x4(&bl[g * 4], stB_lo + off);
            }
#pragma unroll
            for (int mt = 0; mt < 2; mt++)
#pragma unroll
                for (int nt = 0; nt < 4; nt++) {
                    mma_bf16(acc[mt][nt], ah[mt], &bh[nt * 2]);
                    mma_bf16(acc[mt][nt], ah[mt], &bl[nt * 2]);
                    mma_bf16(acc[mt][nt], al[mt], &bh[nt * 2]);
                }
        }

        __syncthreads();            // all warps done with slot before refill
        if (c + 2 < 8) HISSUE(c + 2, slot);
    }

    // ---- logits to smem (reuse A ring region) ----
    float* Lsm = (float*)(smem + HA);    // [128][66]
#pragma unroll
    for (int mt = 0; mt < 2; mt++)
#pragma unroll
        for (int nt = 0; nt < 4; nt++) {
            const int colL = wn + nt * 8 + (l & 3) * 2;
            const int r0 = wm + mt * 16 + (l >> 2);
            *(float2*)(Lsm + r0 * 66 + colL)       = make_float2(acc[mt][nt][0], acc[mt][nt][1]);
            *(float2*)(Lsm + (r0 + 8) * 66 + colL) = make_float2(acc[mt][nt][2], acc[mt][nt][3]);
        }
    __syncthreads();

    // ---- per-agent serial softmax / entropy / value ----
    if (tid < 128) {
        const int agent = mtile * 128 + tid;
        const float* Lr = Lsm + tid * 66;

        float lg[32];
        float mx = -1e30f;
#pragma unroll
        for (int t = 0; t < 32; t++) {
            lg[t] = Lr[t] + bs[t];
            mx = fmaxf(mx, lg[t]);
        }
        float se = 0.f, s1 = 0.f;
#pragma unroll
        for (int t = 0; t < 32; t++) {
            float e = expf(lg[t] - mx);
            se += e;
            s1 += e * lg[t];
        }
        const float lse = mx + logf(se);
        const int act = action[agent];
        const float slp = lg[act & 31] - lse;
        const float ent = lse - s1 / se;
        const float val = Lr[32] + bc[0];

        out[0 * N_AGENTS + agent] = (float)act;
        out[1 * N_AGENTS + agent] = (float)skill[agent];
        out[2 * N_AGENTS + agent] = -2.7725887222397811f;   // -ln(16)
        out[3 * N_AGENTS + agent] = slp;
        out[4 * N_AGENTS + agent] = ent;
        out[5 * N_AGENTS + agent] = val;
    }
}

// ---------------------------------------------------------------------------
// launch
// ---------------------------------------------------------------------------
extern "C" void kernel_launch(void* const* d_in, const int* in_sizes, int n_in,
                              void* d_out, int out_size) {
    (void)in_sizes; (void)n_in; (void)out_size;
    const float* x     = (const float*)d_in[0];
    const float* W_enc = (const float*)d_in[1];
    const float* b_enc = (const float*)d_in[2];
    // d_in[3]=Wm, d_in[4]=bm : dead (selections never returned)
    const float* Ws    = (const float*)d_in[5];
    const float* bs    = (const float*)d_in[6];
    const float* Wc    = (const float*)d_in[7];
    const float* bc    = (const float*)d_in[8];
    const int*   skill = (const int*)d_in[9];
    const int*   act   = (const int*)d_in[10];
    float* out = (float*)d_out;

    unsigned char* dA;
    cudaGetSymbolAddress((void**)&dA, g_Astage);
    unsigned char* dB;
    cudaGetSymbolAddress((void**)&dB, g_Bstage);

    static int cfg_done = 0;
    if (!cfg_done) {
        cudaFuncSetAttribute(enc_gemm_mma, cudaFuncAttributeMaxDynamicSharedMemorySize,
                             SMEM_TOTAL);
        cudaFuncSetAttribute(head_gemm_kernel, cudaFuncAttributeMaxDynamicSharedMemorySize,
                             HEAD_SMEM);
        cfg_done = 1;
    }

    conv_kernel<<<512, 256>>>(W_enc, dB);                 // 512 rows
    conv_kernel<<<N_AGENTS, 256>>>(x, dA);                // 16384 rows

    enc_gemm_mma<<<NTILES * MTILES, 256, SMEM_TOTAL>>>(b_enc);

    head_gemm_kernel<<<MTILES, 256, HEAD_SMEM>>>(Ws, bs, Wc, bc, skill, act, out);
}

// round 7
// speedup vs baseline: 2.9203x; 1.0546x over previous
#include <cuda_runtime.h>
#include <cuda_bf16.h>
#include <stdint.h>

#define N_AGENTS 16384
#define OBS_DIM  2048
#define HID      512

// ---- enc GEMM tiling: BM=128, BN=256, KC=64, 512 threads ----
#define BM 128
#define BN 256
#define KC 64                    // bf16 K per chunk (128B rows)
#define NCHUNK (OBS_DIM / KC)    // 32
#define NTILES (HID / BN)        // 2
#define MTILES (N_AGENTS / BM)   // 128

#define SA_HI 0
#define SA_LO 16384
#define SB_HI 32768
#define SB_LO 65536
#define STAGE 98304              // A 32K + B 64K
#define SMEM_TOTAL (2 * STAGE + 1024)   // 197632

// pre-converted, pre-swizzled tiles (128-row granularity): [tile128][chunk][hi 16K | lo 16K]
__device__ __align__(1024) unsigned char g_Bstage[(size_t)4 * NCHUNK * 32768];
__device__ __align__(1024) unsigned char g_Astage[(size_t)MTILES * NCHUNK * 32768];
// hidden, written by enc epilogue as pre-swizzled hi/lo bf16 head tiles:
// [mtile][hchunk 0..7][hi 16K | lo 16K]
__device__ __align__(1024) unsigned char g_Ahead[(size_t)MTILES * 8 * 32768];

static __device__ __forceinline__ uint32_t smem_addr_u32(const void* p) {
    uint32_t a;
    asm("{ .reg .u64 t; cvta.to.shared.u64 t, %1; cvt.u32.u64 %0, t; }" : "=r"(a) : "l"(p));
    return a;
}

static __device__ __forceinline__ void ldm_x4(uint32_t* r, uint32_t addr) {
    asm volatile("ldmatrix.sync.aligned.m8n8.x4.shared.b16 {%0,%1,%2,%3}, [%4];"
                 : "=r"(r[0]), "=r"(r[1]), "=r"(r[2]), "=r"(r[3]) : "r"(addr));
}

static __device__ __forceinline__ void mma_bf16(float* c, const uint32_t* a,
                                                const uint32_t* b) {
    asm volatile(
        "mma.sync.aligned.m16n8k16.row.col.f32.bf16.bf16.f32 "
        "{%0,%1,%2,%3}, {%4,%5,%6,%7}, {%8,%9}, {%0,%1,%2,%3};"
        : "+f"(c[0]), "+f"(c[1]), "+f"(c[2]), "+f"(c[3])
        : "r"(a[0]), "r"(a[1]), "r"(a[2]), "r"(a[3]), "r"(b[0]), "r"(b[1]));
}

static __device__ __forceinline__ void split2(float x0, float x1, uint32_t& hi, uint32_t& lo) {
    __nv_bfloat16 h0 = __float2bfloat16(x0);
    __nv_bfloat16 h1 = __float2bfloat16(x1);
    __nv_bfloat16 l0 = __float2bfloat16(x0 - __bfloat162float(h0));
    __nv_bfloat16 l1 = __float2bfloat16(x1 - __bfloat162float(h1));
    __nv_bfloat162 hp; hp.x = h0; hp.y = h1;
    __nv_bfloat162 lp; lp.x = l0; lp.y = l1;
    hi = *(uint32_t*)&hp;
    lo = *(uint32_t*)&lp;
}

// ---------------------------------------------------------------------------
// Pre-convert: fp32 [rows x 2048] -> pre-swizzled hi/lo bf16 tile staging.
// Tile = 128 rows x 64 k (hi 16KB | lo 16KB).
// ---------------------------------------------------------------------------
__global__ void conv_kernel(const float* __restrict__ S, unsigned char* __restrict__ D) {
    const int gid = blockIdx.x * 256 + threadIdx.x;
    const int n   = gid >> 8;
    const int k0  = (gid & 255) << 3;
    const float* src = S + (size_t)n * OBS_DIM + k0;
    float4 v0 = *(const float4*)src;
    float4 v1 = *(const float4*)(src + 4);
    float f[8] = {v0.x, v0.y, v0.z, v0.w, v1.x, v1.y, v1.z, v1.w};

    uint32_t hi[4], lo[4];
#pragma unroll
    for (int j = 0; j < 4; j++) split2(f[2 * j], f[2 * j + 1], hi[j], lo[j]);

    const int c  = k0 >> 6;
    const int kl = k0 & 63;
    const int t  = n >> 7;
    const int nl = n & 127;
    const uint32_t byte = (uint32_t)nl * 128 +
                          (((uint32_t)kl * 2) ^ ((uint32_t)(nl & 7) << 4));
    unsigned char* blk = D + ((size_t)(t * NCHUNK + c)) * 32768;
    *(uint4*)(blk + byte)         = make_uint4(hi[0], hi[1], hi[2], hi[3]);
    *(uint4*)(blk + 16384 + byte) = make_uint4(lo[0], lo[1], lo[2], lo[3]);
}

// ---------------------------------------------------------------------------
// HMMA GEMM: relu(x @ W_enc^T + b_enc) -> g_Ahead (bf16 hi/lo tiles)
// BN=256, 512 threads, 2-stage ring, 3-term bf16 hi/lo split.
// ---------------------------------------------------------------------------
__global__ __launch_bounds__(512, 1) void enc_gemm_mma(const float* __restrict__ bias) {
    extern __shared__ __align__(1024) unsigned char smem[];
    const int tid = threadIdx.x;
    const int w = tid >> 5, l = tid & 31;
    const int mtile = blockIdx.x >> 1;
    const int ntile = blockIdx.x & 1;
    const int n0 = ntile * BN;
    const uint32_t sb = smem_addr_u32(smem);
    float* bsm = (float*)(smem + 2 * STAGE);
    if (tid < 256) bsm[tid] = bias[n0 + tid];

    const unsigned char* gA = g_Astage + (size_t)mtile * NCHUNK * 32768;
    const unsigned char* gB0 = g_Bstage + (size_t)(ntile * 2) * NCHUNK * 32768;
    const unsigned char* gB1 = g_Bstage + (size_t)(ntile * 2 + 1) * NCHUNK * 32768;

    float acc[4][4][4];
#pragma unroll
    for (int i = 0; i < 4; i++)
#pragma unroll
        for (int j = 0; j < 4; j++)
#pragma unroll
            for (int q = 0; q < 4; q++) acc[i][j][q] = 0.f;

    const int wm = (w >> 3) * 64;              // 2 m-groups
    const int wn = (w & 7) * 32;               // 8 n-groups
    const int idx = l & 7, seg = l >> 3;
    const int arl = idx + (seg & 1) * 8;       // A row within m16 tile
    const int acb = (seg >> 1) * 16;           // A k-byte sub-offset
    const int brl = idx + (seg >> 1) * 8;      // B row within n16 group
    const int bkb = (seg & 1) * 16;            // B k-byte sub-offset
    const uint32_t sxor = (uint32_t)idx << 4;  // SW128 reduces to this XOR

#define ISSUE(c, slot)                                                          \
    {                                                                           \
        const uint32_t dst = sb + (slot) * STAGE;                               \
        const unsigned char* ga  = gA  + (size_t)(c) * 32768;                   \
        const unsigned char* gb0 = gB0 + (size_t)(c) * 32768;                   \
        const unsigned char* gb1 = gB1 + (size_t)(c) * 32768;                   \
        _Pragma("unroll") for (int i = 0; i < 4; i++) {                         \
            uint32_t off = (uint32_t)(i * 512 + tid) * 16;                      \
            asm volatile("cp.async.cg.shared.global [%0], [%1], 16;"            \
                         :: "r"(dst + off), "l"(ga + off) : "memory");          \
        }                                                                       \
        _Pragma("unroll") for (int i = 0; i < 2; i++) {                         \
            uint32_t off = (uint32_t)(i * 512 + tid) * 16;                      \
            asm volatile("cp.async.cg.shared.global [%0], [%1], 16;"            \
                         :: "r"(dst + SB_HI + off), "l"(gb0 + off) : "memory"); \
            asm volatile("cp.async.cg.shared.global [%0], [%1], 16;"            \
                         :: "r"(dst + SB_HI + 16384 + off), "l"(gb1 + off) : "memory"); \
            asm volatile("cp.async.cg.shared.global [%0], [%1], 16;"            \
                         :: "r"(dst + SB_LO + off), "l"(gb0 + 16384 + off) : "memory"); \
            asm volatile("cp.async.cg.shared.global [%0], [%1], 16;"            \
                         :: "r"(dst + SB_LO + 16384 + off), "l"(gb1 + 16384 + off) : "memory"); \
        }                                                                       \
        asm volatile("cp.async.commit_group;" ::: "memory");                    \
    }

    ISSUE(0, 0);

    for (int c = 0; c < NCHUNK; c++) {
        const int slot = c & 1;
        asm volatile("cp.async.wait_group 0;" ::: "memory");
        __syncthreads();   // chunk c ready; all warps done with slot^1

        if (c + 1 < NCHUNK) ISSUE(c + 1, slot ^ 1);

        const uint32_t stA_hi = sb + slot * STAGE + SA_HI;
        const uint32_t stA_lo = sb + slot * STAGE + SA_LO;
        const uint32_t stB_hi = sb + slot * STAGE + SB_HI;
        const uint32_t stB_lo = sb + slot * STAGE + SB_LO;

#pragma unroll
        for (int ks = 0; ks < 4; ks++) {
            const int kb = ks * 32;
            uint32_t ah[4][4], al[4][4], bh[8], bl[8];
#pragma unroll
            for (int mt = 0; mt < 4; mt++) {
                uint32_t off = (uint32_t)(wm + mt * 16 + arl) * 128 +
                               (((uint32_t)(kb + acb)) ^ sxor);
                ldm_x4(ah[mt], stA_hi + off);
                ldm_x4(al[mt], stA_lo + off);
            }
#pragma unroll
            for (int g = 0; g < 2; g++) {
                uint32_t off = (uint32_t)(wn + g * 16 + brl) * 128 +
                               (((uint32_t)(kb + bkb)) ^ sxor);
                ldm_x4(&bh[g * 4], stB_hi + off);
                ldm_x4(&bl[g * 4], stB_lo + off);
            }
#pragma unroll
            for (int mt = 0; mt < 4; mt++)
#pragma unroll
                for (int nt = 0; nt < 4; nt++) {
                    mma_bf16(acc[mt][nt], ah[mt], &bh[nt * 2]);
                    mma_bf16(acc[mt][nt], ah[mt], &bl[nt * 2]);
                    mma_bf16(acc[mt][nt], al[mt], &bh[nt * 2]);
                }
        }
    }

    // epilogue: bias + relu, write as pre-swizzled hi/lo bf16 head tiles
    unsigned char* gAh = g_Ahead + (size_t)mtile * 8 * 32768;
#pragma unroll
    for (int mt = 0; mt < 4; mt++)
#pragma unroll
        for (int nt = 0; nt < 4; nt++) {
            const int colL = wn + nt * 8 + (l & 3) * 2;
            const float b0 = bsm[colL], b1 = bsm[colL + 1];
            const int rloc = wm + mt * 16 + (l >> 2);
            const int n = n0 + colL;           // global hidden col
            const int cch = n >> 6;            // head chunk
            const int kc = n & 63;
            unsigned char* blk = gAh + (size_t)cch * 32768;

            float v0x = fmaxf(acc[mt][nt][0] + b0, 0.f);
            float v0y = fmaxf(acc[mt][nt][1] + b1, 0.f);
            float v1x = fmaxf(acc[mt][nt][2] + b0, 0.f);
            float v1y = fmaxf(acc[mt][nt][3] + b1, 0.f);

            uint32_t h01, l01, h23, l23;
            split2(v0x, v0y, h01, l01);
            split2(v1x, v1y, h23, l23);

            const uint32_t by0 = (uint32_t)rloc * 128 +
                                 (((uint32_t)(2 * kc)) ^ ((uint32_t)(rloc & 7) << 4));
            const int r1 = rloc + 8;
            const uint32_t by1 = (uint32_t)r1 * 128 +
                                 (((uint32_t)(2 * kc)) ^ ((uint32_t)(r1 & 7) << 4));
            *(uint32_t*)(blk + by0)         = h01;
            *(uint32_t*)(blk + 16384 + by0) = l01;
            *(uint32_t*)(blk + by1)         = h23;
            *(uint32_t*)(blk + 16384 + by1) = l23;
        }
}

// ---------------------------------------------------------------------------
// Head: per mtile, HMMA [128 x 64 x 512] of hidden vs W'=[Ws;Wc;0pad],
// then per-agent serial softmax/entropy/value. 3-term bf16 hi/lo. (R6-proven)
// ---------------------------------------------------------------------------
#define HB_H 0                     // W' hi: 8 chunks x 8KB
#define HB_L 65536                 // W' lo: 8 chunks x 8KB
#define HA   131072                // A ring: 2 x 32KB (reused for logits after)
#define HSTAGE 32768
#define HEAD_SMEM (HA + 2 * HSTAGE)  // 196608

__global__ __launch_bounds__(256, 1) void head_gemm_kernel(
    const float* __restrict__ Ws, const float* __restrict__ bs,
    const float* __restrict__ Wc, const float* __restrict__ bc,
    const int* __restrict__ skill, const int* __restrict__ action,
    float* __restrict__ out)
{
    extern __shared__ __align__(1024) unsigned char smem[];
    const int tid = threadIdx.x;
    const int w = tid >> 5, l = tid & 31;
    const int mtile = blockIdx.x;
    const uint32_t sb = smem_addr_u32(smem);

    // ---- build W' tile: rows 0-31 = Ws, row 32 = Wc, rows 33-63 = 0 ----
#pragma unroll
    for (int it = 0; it < 16; it++) {
        const int u = it * 256 + tid;
        const int row = u >> 6;
        const int k0 = (u & 63) << 3;
        float f[8];
        if (row < 32) {
            const float4* s4 = (const float4*)(Ws + (size_t)row * HID + k0);
            *(float4*)(f) = s4[0];
            *(float4*)(f + 4) = s4[1];
        } else if (row == 32) {
            const float4* s4 = (const float4*)(Wc + k0);
            *(float4*)(f) = s4[0];
            *(float4*)(f + 4) = s4[1];
        } else {
#pragma unroll
            for (int e = 0; e < 8; e++) f[e] = 0.f;
        }
        uint32_t hi[4], lo[4];
#pragma unroll
        for (int j = 0; j < 4; j++) split2(f[2 * j], f[2 * j + 1], hi[j], lo[j]);
        const int c = k0 >> 6;
        const int kl = k0 & 63;
        const uint32_t byte = (uint32_t)row * 128 +
                              (((uint32_t)kl * 2) ^ ((uint32_t)(row & 7) << 4));
        *(uint4*)(smem + HB_H + c * 8192 + byte) = make_uint4(hi[0], hi[1], hi[2], hi[3]);
        *(uint4*)(smem + HB_L + c * 8192 + byte) = make_uint4(lo[0], lo[1], lo[2], lo[3]);
    }

    const unsigned char* gA = g_Ahead + (size_t)mtile * 8 * 32768;

    float acc[2][4][4];
#pragma unroll
    for (int i = 0; i < 2; i++)
#pragma unroll
        for (int j = 0; j < 4; j++)
#pragma unroll
            for (int q = 0; q < 4; q++) acc[i][j][q] = 0.f;

    const int wm = (w >> 1) * 32;
    const int wn = (w & 1) * 32;
    const int idx = l & 7, seg = l >> 3;
    const int arl = idx + (seg & 1) * 8;
    const int acb = (seg >> 1) * 16;
    const int brl = idx + (seg >> 1) * 8;
    const int bkb = (seg & 1) * 16;
    const uint32_t sxor = (uint32_t)idx << 4;

#define HISSUE(c, slot)                                                        \
    {                                                                          \
        const uint32_t dst = sb + HA + (slot) * HSTAGE;                        \
        const unsigned char* ga = gA + (size_t)(c) * 32768;                    \
        _Pragma("unroll") for (int i = 0; i < 8; i++) {                        \
            uint32_t off = (uint32_t)(i * 256 + tid) * 16;                     \
            asm volatile("cp.async.cg.shared.global [%0], [%1], 16;"           \
                         :: "r"(dst + off), "l"(ga + off) : "memory");         \
        }                                                                      \
        asm volatile("cp.async.commit_group;" ::: "memory");                   \
    }

    HISSUE(0, 0);
    HISSUE(1, 1);
    __syncthreads();   // W' tile ready

    for (int c = 0; c < 8; c++) {
        const int slot = c & 1;
        if (c < 6) {
            asm volatile("cp.async.wait_group 1;" ::: "memory");
        } else {
            asm volatile("cp.async.wait_group 0;" ::: "memory");
        }
        __syncthreads();

        const uint32_t stA_hi = sb + HA + slot * HSTAGE;
        const uint32_t stA_lo = stA_hi + 16384;
        const uint32_t stB_hi = sb + HB_H + c * 8192;
        const uint32_t stB_lo = sb + HB_L + c * 8192;

#pragma unroll
        for (int ks = 0; ks < 4; ks++) {
            const int kb = ks * 32;
            uint32_t ah[2][4], al[2][4], bh[8], bl[8];
#pragma unroll
            for (int mt = 0; mt < 2; mt++) {
                uint32_t off = (uint32_t)(wm + mt * 16 + arl) * 128 +
                               (((uint32_t)(kb + acb)) ^ sxor);
                ldm_x4(ah[mt], stA_hi + off);
                ldm_x4(al[mt], stA_lo + off);
            }
#pragma unroll
            for (int g = 0; g < 2; g++) {
                uint32_t off = (uint32_t)(wn + g * 16 + brl) * 128 +
                               (((uint32_t)(kb + bkb)) ^ sxor);
                ldm_x4(&bh[g * 4], stB_hi + off);
                ldm_x4(&bl[g * 4], stB_lo + off);
            }
#pragma unroll
            for (int mt = 0; mt < 2; mt++)
#pragma unroll
                for (int nt = 0; nt < 4; nt++) {
                    mma_bf16(acc[mt][nt], ah[mt], &bh[nt * 2]);
                    mma_bf16(acc[mt][nt], ah[mt], &bl[nt * 2]);
                    mma_bf16(acc[mt][nt], al[mt], &bh[nt * 2]);
                }
        }

        __syncthreads();
        if (c + 2 < 8) HISSUE(c + 2, slot);
    }

    // ---- logits to smem (reuse A ring region) ----
    float* Lsm = (float*)(smem + HA);    // [128][66]
#pragma unroll
    for (int mt = 0; mt < 2; mt++)
#pragma unroll
        for (int nt = 0; nt < 4; nt++) {
            const int colL = wn + nt * 8 + (l & 3) * 2;
            const int r0 = wm + mt * 16 + (l >> 2);
            *(float2*)(Lsm + r0 * 66 + colL)       = make_float2(acc[mt][nt][0], acc[mt][nt][1]);
            *(float2*)(Lsm + (r0 + 8) * 66 + colL) = make_float2(acc[mt][nt][2], acc[mt][nt][3]);
        }
    __syncthreads();

    // ---- per-agent serial softmax / entropy / value ----
    if (tid < 128) {
        const int agent = mtile * 128 + tid;
        const float* Lr = Lsm + tid * 66;

        float lg[32];
        float mx = -1e30f;
#pragma unroll
        for (int t = 0; t < 32; t++) {
            lg[t] = Lr[t] + bs[t];
            mx = fmaxf(mx, lg[t]);
        }
        float se = 0.f, s1 = 0.f;
#pragma unroll
        for (int t = 0; t < 32; t++) {
            float e = expf(lg[t] - mx);
            se += e;
            s1 += e * lg[t];
        }
        const float lse = mx + logf(se);
        const int act = action[agent];
        const float slp = lg[act & 31] - lse;
        const float ent = lse - s1 / se;
        const float val = Lr[32] + bc[0];

        out[0 * N_AGENTS + agent] = (float)act;
        out[1 * N_AGENTS + agent] = (float)skill[agent];
        out[2 * N_AGENTS + agent] = -2.7725887222397811f;   // -ln(16)
        out[3 * N_AGENTS + agent] = slp;
        out[4 * N_AGENTS + agent] = ent;
        out[5 * N_AGENTS + agent] = val;
    }
}

// ---------------------------------------------------------------------------
// launch
// ---------------------------------------------------------------------------
extern "C" void kernel_launch(void* const* d_in, const int* in_sizes, int n_in,
                              void* d_out, int out_size) {
    (void)in_sizes; (void)n_in; (void)out_size;
    const float* x     = (const float*)d_in[0];
    const float* W_enc = (const float*)d_in[1];
    const float* b_enc = (const float*)d_in[2];
    // d_in[3]=Wm, d_in[4]=bm : dead (selections never returned)
    const float* Ws    = (const float*)d_in[5];
    const float* bs    = (const float*)d_in[6];
    const float* Wc    = (const float*)d_in[7];
    const float* bc    = (const float*)d_in[8];
    const int*   skill = (const int*)d_in[9];
    const int*   act   = (const int*)d_in[10];
    float* out = (float*)d_out;

    unsigned char* dA;
    cudaGetSymbolAddress((void**)&dA, g_Astage);
    unsigned char* dB;
    cudaGetSymbolAddress((void**)&dB, g_Bstage);

    static int cfg_done = 0;
    if (!cfg_done) {
        cudaFuncSetAttribute(enc_gemm_mma, cudaFuncAttributeMaxDynamicSharedMemorySize,
                             SMEM_TOTAL);
        cudaFuncSetAttribute(head_gemm_kernel, cudaFuncAttributeMaxDynamicSharedMemorySize,
                             HEAD_SMEM);
        cfg_done = 1;
    }

    conv_kernel<<<512, 256>>>(W_enc, dB);                 // 512 rows
    conv_kernel<<<N_AGENTS, 256>>>(x, dA);                // 16384 rows

    enc_gemm_mma<<<NTILES * MTILES, 512, SMEM_TOTAL>>>(b_enc);

    head_gemm_kernel<<<MTILES, 256, HEAD_SMEM>>>(Ws, bs, Wc, bc, skill, act, out);
}

// round 8
// speedup vs baseline: 3.8494x; 1.3181x over previous
#include <cuda_runtime.h>
#include <cuda_bf16.h>
#include <cuda_fp16.h>
#include <stdint.h>

#define N_AGENTS 16384
#define OBS_DIM  2048
#define HID      512

// ---- enc GEMM tiling: BM=128, BN=256, KC=64, 512 threads, 2-term fp16 ----
#define BM 128
#define BN 256
#define KC 64                    // fp16 K per chunk (128B rows)
#define NCHUNK (OBS_DIM / KC)    // 32
#define NTILES (HID / BN)        // 2
#define MTILES (N_AGENTS / BM)   // 128

#define SB_HI 16384              // B hi plane (256 rows x 128B)
#define SB_LO 49152              // B lo plane
#define STAGE 81920              // A 16K + B 64K
#define SMEM_TOTAL (2 * STAGE + 1024)   // 164864

// B: pre-converted fp16 hi/lo, [tile128][chunk][hi 16K | lo 16K]
__device__ __align__(1024) unsigned char g_Bstage[(size_t)4 * NCHUNK * 32768];
// A: pre-converted single fp16, [mtile][chunk][16K]
__device__ __align__(1024) unsigned char g_Astage[(size_t)MTILES * NCHUNK * 16384];
// hidden, written by enc epilogue as pre-swizzled hi/lo bf16 head tiles:
// [mtile][hchunk 0..7][hi 16K | lo 16K]
__device__ __align__(1024) unsigned char g_Ahead[(size_t)MTILES * 8 * 32768];

static __device__ __forceinline__ uint32_t smem_addr_u32(const void* p) {
    uint32_t a;
    asm("{ .reg .u64 t; cvta.to.shared.u64 t, %1; cvt.u32.u64 %0, t; }" : "=r"(a) : "l"(p));
    return a;
}

static __device__ __forceinline__ void ldm_x4(uint32_t* r, uint32_t addr) {
    asm volatile("ldmatrix.sync.aligned.m8n8.x4.shared.b16 {%0,%1,%2,%3}, [%4];"
                 : "=r"(r[0]), "=r"(r[1]), "=r"(r[2]), "=r"(r[3]) : "r"(addr));
}

static __device__ __forceinline__ void mma_f16(float* c, const uint32_t* a,
                                               const uint32_t* b) {
    asm volatile(
        "mma.sync.aligned.m16n8k16.row.col.f32.f16.f16.f32 "
        "{%0,%1,%2,%3}, {%4,%5,%6,%7}, {%8,%9}, {%0,%1,%2,%3};"
        : "+f"(c[0]), "+f"(c[1]), "+f"(c[2]), "+f"(c[3])
        : "r"(a[0]), "r"(a[1]), "r"(a[2]), "r"(a[3]), "r"(b[0]), "r"(b[1]));
}

static __device__ __forceinline__ void mma_bf16(float* c, const uint32_t* a,
                                                const uint32_t* b) {
    asm volatile(
        "mma.sync.aligned.m16n8k16.row.col.f32.bf16.bf16.f32 "
        "{%0,%1,%2,%3}, {%4,%5,%6,%7}, {%8,%9}, {%0,%1,%2,%3};"
        : "+f"(c[0]), "+f"(c[1]), "+f"(c[2]), "+f"(c[3])
        : "r"(a[0]), "r"(a[1]), "r"(a[2]), "r"(a[3]), "r"(b[0]), "r"(b[1]));
}

// bf16 hi/lo split (head path)
static __device__ __forceinline__ void split2(float x0, float x1, uint32_t& hi, uint32_t& lo) {
    __nv_bfloat16 h0 = __float2bfloat16(x0);
    __nv_bfloat16 h1 = __float2bfloat16(x1);
    __nv_bfloat16 l0 = __float2bfloat16(x0 - __bfloat162float(h0));
    __nv_bfloat16 l1 = __float2bfloat16(x1 - __bfloat162float(h1));
    __nv_bfloat162 hp; hp.x = h0; hp.y = h1;
    __nv_bfloat162 lp; lp.x = l0; lp.y = l1;
    hi = *(uint32_t*)&hp;
    lo = *(uint32_t*)&lp;
}

// fp16 hi/lo split (enc B path)
static __device__ __forceinline__ void split2h(float x0, float x1, uint32_t& hi, uint32_t& lo) {
    __half h0 = __float2half_rn(x0);
    __half h1 = __float2half_rn(x1);
    __half l0 = __float2half_rn(x0 - __half2float(h0));
    __half l1 = __float2half_rn(x1 - __half2float(h1));
    __half2 hp; hp.x = h0; hp.y = h1;
    __half2 lp; lp.x = l0; lp.y = l1;
    hi = *(uint32_t*)&hp;
    lo = *(uint32_t*)&lp;
}

// ---------------------------------------------------------------------------
// conv_x: fp32 -> single fp16 plane, pre-swizzled. Tile = 128 rows x 64 k (16KB)
// ---------------------------------------------------------------------------
__global__ void conv_x_kernel(const float* __restrict__ S, unsigned char* __restrict__ D) {
    const int gid = blockIdx.x * 256 + threadIdx.x;
    const int n   = gid >> 8;
    const int k0  = (gid & 255) << 3;
    const float* src = S + (size_t)n * OBS_DIM + k0;
    float4 v0 = *(const float4*)src;
    float4 v1 = *(const float4*)(src + 4);
    float f[8] = {v0.x, v0.y, v0.z, v0.w, v1.x, v1.y, v1.z, v1.w};

    uint32_t hv[4];
#pragma unroll
    for (int j = 0; j < 4; j++) {
        __half2 hp;
        hp.x = __float2half_rn(f[2 * j]);
        hp.y = __float2half_rn(f[2 * j + 1]);
        hv[j] = *(uint32_t*)&hp;
    }

    const int c  = k0 >> 6;
    const int kl = k0 & 63;
    const int t  = n >> 7;
    const int nl = n & 127;
    const uint32_t byte = (uint32_t)nl * 128 +
                          (((uint32_t)kl * 2) ^ ((uint32_t)(nl & 7) << 4));
    unsigned char* blk = D + ((size_t)(t * NCHUNK + c)) * 16384;
    *(uint4*)(blk + byte) = make_uint4(hv[0], hv[1], hv[2], hv[3]);
}

// ---------------------------------------------------------------------------
// conv_w: fp32 -> fp16 hi/lo planes, pre-swizzled. [tile128][chunk][hi|lo]
// ---------------------------------------------------------------------------
__global__ void conv_w_kernel(const float* __restrict__ S, unsigned char* __restrict__ D) {
    const int gid = blockIdx.x * 256 + threadIdx.x;
    const int n   = gid >> 8;
    const int k0  = (gid & 255) << 3;
    const float* src = S + (size_t)n * OBS_DIM + k0;
    float4 v0 = *(const float4*)src;
    float4 v1 = *(const float4*)(src + 4);
    float f[8] = {v0.x, v0.y, v0.z, v0.w, v1.x, v1.y, v1.z, v1.w};

    uint32_t hi[4], lo[4];
#pragma unroll
    for (int j = 0; j < 4; j++) split2h(f[2 * j], f[2 * j + 1], hi[j], lo[j]);

    const int c  = k0 >> 6;
    const int kl = k0 & 63;
    const int t  = n >> 7;
    const int nl = n & 127;
    const uint32_t byte = (uint32_t)nl * 128 +
                          (((uint32_t)kl * 2) ^ ((uint32_t)(nl & 7) << 4));
    unsigned char* blk = D + ((size_t)(t * NCHUNK + c)) * 32768;
    *(uint4*)(blk + byte)         = make_uint4(hi[0], hi[1], hi[2], hi[3]);
    *(uint4*)(blk + 16384 + byte) = make_uint4(lo[0], lo[1], lo[2], lo[3]);
}

// ---------------------------------------------------------------------------
// HMMA GEMM, 2-term fp16: relu(x @ W_enc^T + b_enc) -> g_Ahead (bf16 hi/lo)
// D = a * (b_hi + b_lo). BN=256, 512 threads, 2-stage ring.
// ---------------------------------------------------------------------------
__global__ __launch_bounds__(512, 1) void enc_gemm_mma(const float* __restrict__ bias) {
    extern __shared__ __align__(1024) unsigned char smem[];
    const int tid = threadIdx.x;
    const int w = tid >> 5, l = tid & 31;
    const int mtile = blockIdx.x >> 1;
    const int ntile = blockIdx.x & 1;
    const int n0 = ntile * BN;
    const uint32_t sb = smem_addr_u32(smem);
    float* bsm = (float*)(smem + 2 * STAGE);
    if (tid < 256) bsm[tid] = bias[n0 + tid];

    const unsigned char* gA = g_Astage + (size_t)mtile * NCHUNK * 16384;
    const unsigned char* gB0 = g_Bstage + (size_t)(ntile * 2) * NCHUNK * 32768;
    const unsigned char* gB1 = g_Bstage + (size_t)(ntile * 2 + 1) * NCHUNK * 32768;

    float acc[4][4][4];
#pragma unroll
    for (int i = 0; i < 4; i++)
#pragma unroll
        for (int j = 0; j < 4; j++)
#pragma unroll
            for (int q = 0; q < 4; q++) acc[i][j][q] = 0.f;

    const int wm = (w >> 3) * 64;
    const int wn = (w & 7) * 32;
    const int idx = l & 7, seg = l >> 3;
    const int arl = idx + (seg & 1) * 8;
    const int acb = (seg >> 1) * 16;
    const int brl = idx + (seg >> 1) * 8;
    const int bkb = (seg & 1) * 16;
    const uint32_t sxor = (uint32_t)idx << 4;

#define ISSUE(c, slot)                                                          \
    {                                                                           \
        const uint32_t dst = sb + (slot) * STAGE;                               \
        const unsigned char* ga  = gA  + (size_t)(c) * 16384;                   \
        const unsigned char* gb0 = gB0 + (size_t)(c) * 32768;                   \
        const unsigned char* gb1 = gB1 + (size_t)(c) * 32768;                   \
        _Pragma("unroll") for (int i = 0; i < 2; i++) {                         \
            uint32_t off = (uint32_t)(i * 512 + tid) * 16;                      \
            asm volatile("cp.async.cg.shared.global [%0], [%1], 16;"            \
                         :: "r"(dst + off), "l"(ga + off) : "memory");          \
            asm volatile("cp.async.cg.shared.global [%0], [%1], 16;"            \
                         :: "r"(dst + SB_HI + off), "l"(gb0 + off) : "memory"); \
            asm volatile("cp.async.cg.shared.global [%0], [%1], 16;"            \
                         :: "r"(dst + SB_HI + 16384 + off), "l"(gb1 + off) : "memory"); \
            asm volatile("cp.async.cg.shared.global [%0], [%1], 16;"            \
                         :: "r"(dst + SB_LO + off), "l"(gb0 + 16384 + off) : "memory"); \
            asm volatile("cp.async.cg.shared.global [%0], [%1], 16;"            \
                         :: "r"(dst + SB_LO + 16384 + off), "l"(gb1 + 16384 + off) : "memory"); \
        }                                                                       \
        asm volatile("cp.async.commit_group;" ::: "memory");                    \
    }

    ISSUE(0, 0);

    for (int c = 0; c < NCHUNK; c++) {
        const int slot = c & 1;
        asm volatile("cp.async.wait_group 0;" ::: "memory");
        __syncthreads();

        if (c + 1 < NCHUNK) ISSUE(c + 1, slot ^ 1);

        const uint32_t stA    = sb + slot * STAGE;
        const uint32_t stB_hi = sb + slot * STAGE + SB_HI;
        const uint32_t stB_lo = sb + slot * STAGE + SB_LO;

#pragma unroll
        for (int ks = 0; ks < 4; ks++) {
            const int kb = ks * 32;
            uint32_t a[4][4], bh[8], bl[8];
#pragma unroll
            for (int mt = 0; mt < 4; mt++) {
                uint32_t off = (uint32_t)(wm + mt * 16 + arl) * 128 +
                               (((uint32_t)(kb + acb)) ^ sxor);
                ldm_x4(a[mt], stA + off);
            }
#pragma unroll
            for (int g = 0; g < 2; g++) {
                uint32_t off = (uint32_t)(wn + g * 16 + brl) * 128 +
                               (((uint32_t)(kb + bkb)) ^ sxor);
                ldm_x4(&bh[g * 4], stB_hi + off);
                ldm_x4(&bl[g * 4], stB_lo + off);
            }
#pragma unroll
            for (int mt = 0; mt < 4; mt++)
#pragma unroll
                for (int nt = 0; nt < 4; nt++) {
                    mma_f16(acc[mt][nt], a[mt], &bh[nt * 2]);
                    mma_f16(acc[mt][nt], a[mt], &bl[nt * 2]);
                }
        }
    }

    // epilogue: bias + relu, write as pre-swizzled hi/lo bf16 head tiles
    unsigned char* gAh = g_Ahead + (size_t)mtile * 8 * 32768;
#pragma unroll
    for (int mt = 0; mt < 4; mt++)
#pragma unroll
        for (int nt = 0; nt < 4; nt++) {
            const int colL = wn + nt * 8 + (l & 3) * 2;
            const float b0 = bsm[colL], b1 = bsm[colL + 1];
            const int rloc = wm + mt * 16 + (l >> 2);
            const int n = n0 + colL;
            const int cch = n >> 6;
            const int kc = n & 63;
            unsigned char* blk = gAh + (size_t)cch * 32768;

            float v0x = fmaxf(acc[mt][nt][0] + b0, 0.f);
            float v0y = fmaxf(acc[mt][nt][1] + b1, 0.f);
            float v1x = fmaxf(acc[mt][nt][2] + b0, 0.f);
            float v1y = fmaxf(acc[mt][nt][3] + b1, 0.f);

            uint32_t h01, l01, h23, l23;
            split2(v0x, v0y, h01, l01);
            split2(v1x, v1y, h23, l23);

            const uint32_t by0 = (uint32_t)rloc * 128 +
                                 (((uint32_t)(2 * kc)) ^ ((uint32_t)(rloc & 7) << 4));
            const int r1 = rloc + 8;
            const uint32_t by1 = (uint32_t)r1 * 128 +
                                 (((uint32_t)(2 * kc)) ^ ((uint32_t)(r1 & 7) << 4));
            *(uint32_t*)(blk + by0)         = h01;
            *(uint32_t*)(blk + 16384 + by0) = l01;
            *(uint32_t*)(blk + by1)         = h23;
            *(uint32_t*)(blk + 16384 + by1) = l23;
        }
}

// ---------------------------------------------------------------------------
// Head (R6/R7-proven): per mtile HMMA [128 x 64 x 512] vs W'=[Ws;Wc;0pad],
// 3-term bf16 hi/lo, then per-agent serial softmax/entropy/value.
// ---------------------------------------------------------------------------
#define HB_H 0
#define HB_L 65536
#define HA   131072
#define HSTAGE 32768
#define HEAD_SMEM (HA + 2 * HSTAGE)  // 196608

__global__ __launch_bounds__(256, 1) void head_gemm_kernel(
    const float* __restrict__ Ws, const float* __restrict__ bs,
    const float* __restrict__ Wc, const float* __restrict__ bc,
    const int* __restrict__ skill, const int* __restrict__ action,
    float* __restrict__ out)
{
    extern __shared__ __align__(1024) unsigned char smem[];
    const int tid = threadIdx.x;
    const int w = tid >> 5, l = tid & 31;
    const int mtile = blockIdx.x;
    const uint32_t sb = smem_addr_u32(smem);

#pragma unroll
    for (int it = 0; it < 16; it++) {
        const int u = it * 256 + tid;
        const int row = u >> 6;
        const int k0 = (u & 63) << 3;
        float f[8];
        if (row < 32) {
            const float4* s4 = (const float4*)(Ws + (size_t)row * HID + k0);
            *(float4*)(f) = s4[0];
            *(float4*)(f + 4) = s4[1];
        } else if (row == 32) {
            const float4* s4 = (const float4*)(Wc + k0);
            *(float4*)(f) = s4[0];
            *(float4*)(f + 4) = s4[1];
        } else {
#pragma unroll
            for (int e = 0; e < 8; e++) f[e] = 0.f;
        }
        uint32_t hi[4], lo[4];
#pragma unroll
        for (int j = 0; j < 4; j++) split2(f[2 * j], f[2 * j + 1], hi[j], lo[j]);
        const int c = k0 >> 6;
        const int kl = k0 & 63;
        const uint32_t byte = (uint32_t)row * 128 +
                              (((uint32_t)kl * 2) ^ ((uint32_t)(row & 7) << 4));
        *(uint4*)(smem + HB_H + c * 8192 + byte) = make_uint4(hi[0], hi[1], hi[2], hi[3]);
        *(uint4*)(smem + HB_L + c * 8192 + byte) = make_uint4(lo[0], lo[1], lo[2], lo[3]);
    }

    const unsigned char* gA = g_Ahead + (size_t)mtile * 8 * 32768;

    float acc[2][4][4];
#pragma unroll
    for (int i = 0; i < 2; i++)
#pragma unroll
        for (int j = 0; j < 4; j++)
#pragma unroll
            for (int q = 0; q < 4; q++) acc[i][j][q] = 0.f;

    const int wm = (w >> 1) * 32;
    const int wn = (w & 1) * 32;
    const int idx = l & 7, seg = l >> 3;
    const int arl = idx + (seg & 1) * 8;
    const int acb = (seg >> 1) * 16;
    const int brl = idx + (seg >> 1) * 8;
    const int bkb = (seg & 1) * 16;
    const uint32_t sxor = (uint32_t)idx << 4;

#define HISSUE(c, slot)                                                        \
    {                                                                          \
        const uint32_t dst = sb + HA + (slot) * HSTAGE;                        \
        const unsigned char* ga = gA + (size_t)(c) * 32768;                    \
        _Pragma("unroll") for (int i = 0; i < 8; i++) {                        \
            uint32_t off = (uint32_t)(i * 256 + tid) * 16;                     \
            asm volatile("cp.async.cg.shared.global [%0], [%1], 16;"           \
                         :: "r"(dst + off), "l"(ga + off) : "memory");         \
        }                                                                      \
        asm volatile("cp.async.commit_group;" ::: "memory");                   \
    }

    HISSUE(0, 0);
    HISSUE(1, 1);
    __syncthreads();

    for (int c = 0; c < 8; c++) {
        const int slot = c & 1;
        if (c < 6) {
            asm volatile("cp.async.wait_group 1;" ::: "memory");
        } else {
            asm volatile("cp.async.wait_group 0;" ::: "memory");
        }
        __syncthreads();

        const uint32_t stA_hi = sb + HA + slot * HSTAGE;
        const uint32_t stA_lo = stA_hi + 16384;
        const uint32_t stB_hi = sb + HB_H + c * 8192;
        const uint32_t stB_lo = sb + HB_L + c * 8192;

#pragma unroll
        for (int ks = 0; ks < 4; ks++) {
            const int kb = ks * 32;
            uint32_t ah[2][4], al[2][4], bh[8], bl[8];
#pragma unroll
            for (int mt = 0; mt < 2; mt++) {
                uint32_t off = (uint32_t)(wm + mt * 16 + arl) * 128 +
                               (((uint32_t)(kb + acb)) ^ sxor);
                ldm_x4(ah[mt], stA_hi + off);
                ldm_x4(al[mt], stA_lo + off);
            }
#pragma unroll
            for (int g = 0; g < 2; g++) {
                uint32_t off = (uint32_t)(wn + g * 16 + brl) * 128 +
                               (((uint32_t)(kb + bkb)) ^ sxor);
                ldm_x4(&bh[g * 4], stB_hi + off);
                ldm_x4(&bl[g * 4], stB_lo + off);
            }
#pragma unroll
            for (int mt = 0; mt < 2; mt++)
#pragma unroll
                for (int nt = 0; nt < 4; nt++) {
                    mma_bf16(acc[mt][nt], ah[mt], &bh[nt * 2]);
                    mma_bf16(acc[mt][nt], ah[mt], &bl[nt * 2]);
                    mma_bf16(acc[mt][nt], al[mt], &bh[nt * 2]);
                }
        }

        __syncthreads();
        if (c + 2 < 8) HISSUE(c + 2, slot);
    }

    float* Lsm = (float*)(smem + HA);
#pragma unroll
    for (int mt = 0; mt < 2; mt++)
#pragma unroll
        for (int nt = 0; nt < 4; nt++) {
            const int colL = wn + nt * 8 + (l & 3) * 2;
            const int r0 = wm + mt * 16 + (l >> 2);
            *(float2*)(Lsm + r0 * 66 + colL)       = make_float2(acc[mt][nt][0], acc[mt][nt][1]);
            *(float2*)(Lsm + (r0 + 8) * 66 + colL) = make_float2(acc[mt][nt][2], acc[mt][nt][3]);
        }
    __syncthreads();

    if (tid < 128) {
        const int agent = mtile * 128 + tid;
        const float* Lr = Lsm + tid * 66;

        float lg[32];
        float mx = -1e30f;
#pragma unroll
        for (int t = 0; t < 32; t++) {
            lg[t] = Lr[t] + bs[t];
            mx = fmaxf(mx, lg[t]);
        }
        float se = 0.f, s1 = 0.f;
#pragma unroll
        for (int t = 0; t < 32; t++) {
            float e = expf(lg[t] - mx);
            se += e;
            s1 += e * lg[t];
        }
        const float lse = mx + logf(se);
        const int act = action[agent];
        const float slp = lg[act & 31] - lse;
        const float ent = lse - s1 / se;
        const float val = Lr[32] + bc[0];

        out[0 * N_AGENTS + agent] = (float)act;
        out[1 * N_AGENTS + agent] = (float)skill[agent];
        out[2 * N_AGENTS + agent] = -2.7725887222397811f;   // -ln(16)
        out[3 * N_AGENTS + agent] = slp;
        out[4 * N_AGENTS + agent] = ent;
        out[5 * N_AGENTS + agent] = val;
    }
}

// ---------------------------------------------------------------------------
// launch
// ---------------------------------------------------------------------------
extern "C" void kernel_launch(void* const* d_in, const int* in_sizes, int n_in,
                              void* d_out, int out_size) {
    (void)in_sizes; (void)n_in; (void)out_size;
    const float* x     = (const float*)d_in[0];
    const float* W_enc = (const float*)d_in[1];
    const float* b_enc = (const float*)d_in[2];
    // d_in[3]=Wm, d_in[4]=bm : dead (selections never returned)
    const float* Ws    = (const float*)d_in[5];
    const float* bs    = (const float*)d_in[6];
    const float* Wc    = (const float*)d_in[7];
    const float* bc    = (const float*)d_in[8];
    const int*   skill = (const int*)d_in[9];
    const int*   act   = (const int*)d_in[10];
    float* out = (float*)d_out;

    unsigned char* dA;
    cudaGetSymbolAddress((void**)&dA, g_Astage);
    unsigned char* dB;
    cudaGetSymbolAddress((void**)&dB, g_Bstage);

    static int cfg_done = 0;
    if (!cfg_done) {
        cudaFuncSetAttribute(enc_gemm_mma, cudaFuncAttributeMaxDynamicSharedMemorySize,
                             SMEM_TOTAL);
        cudaFuncSetAttribute(head_gemm_kernel, cudaFuncAttributeMaxDynamicSharedMemorySize,
                             HEAD_SMEM);
        cfg_done = 1;
    }

    conv_w_kernel<<<512, 256>>>(W_enc, dB);               // 512 rows, hi/lo
    conv_x_kernel<<<N_AGENTS, 256>>>(x, dA);              // 16384 rows, single fp16

    enc_gemm_mma<<<NTILES * MTILES, 512, SMEM_TOTAL>>>(b_enc);

    head_gemm_kernel<<<MTILES, 256, HEAD_SMEM>>>(Ws, bs, Wc, bc, skill, act, out);
}

// round 9
// speedup vs baseline: 5.7766x; 1.5006x over previous
#include <cuda_runtime.h>
#include <cuda_bf16.h>
#include <cuda_fp16.h>
#include <stdint.h>

#define N_AGENTS 16384
#define OBS_DIM  2048
#define HID      512

// ---- enc GEMM tiling: BM=128, BN=256, KC=64, 512 threads, 1-term fp16 ----
#define BM 128
#define BN 256
#define KC 64                    // fp16 K per chunk (128B rows)
#define NCHUNK (OBS_DIM / KC)    // 32
#define NTILES (HID / BN)        // 2
#define MTILES (N_AGENTS / BM)   // 128

#define SB_OFF 16384             // B plane (256 rows x 128B) after A (128 rows)
#define STAGE 49152              // A 16K + B 32K
#define NSTAGE 3
#define SMEM_TOTAL (NSTAGE * STAGE + 1024)   // 148480

// B: pre-converted single fp16, [tile128][chunk][16K]
__device__ __align__(1024) unsigned char g_Bstage[(size_t)4 * NCHUNK * 16384];
// A: pre-converted single fp16, [mtile][chunk][16K]
__device__ __align__(1024) unsigned char g_Astage[(size_t)MTILES * NCHUNK * 16384];
// hidden, written by enc epilogue as pre-swizzled hi/lo bf16 head tiles:
// [mtile][hchunk 0..7][hi 16K | lo 16K]
__device__ __align__(1024) unsigned char g_Ahead[(size_t)MTILES * 8 * 32768];

static __device__ __forceinline__ uint32_t smem_addr_u32(const void* p) {
    uint32_t a;
    asm("{ .reg .u64 t; cvta.to.shared.u64 t, %1; cvt.u32.u64 %0, t; }" : "=r"(a) : "l"(p));
    return a;
}

static __device__ __forceinline__ void ldm_x4(uint32_t* r, uint32_t addr) {
    asm volatile("ldmatrix.sync.aligned.m8n8.x4.shared.b16 {%0,%1,%2,%3}, [%4];"
                 : "=r"(r[0]), "=r"(r[1]), "=r"(r[2]), "=r"(r[3]) : "r"(addr));
}

static __device__ __forceinline__ void mma_f16(float* c, const uint32_t* a,
                                               const uint32_t* b) {
    asm volatile(
        "mma.sync.aligned.m16n8k16.row.col.f32.f16.f16.f32 "
        "{%0,%1,%2,%3}, {%4,%5,%6,%7}, {%8,%9}, {%0,%1,%2,%3};"
        : "+f"(c[0]), "+f"(c[1]), "+f"(c[2]), "+f"(c[3])
        : "r"(a[0]), "r"(a[1]), "r"(a[2]), "r"(a[3]), "r"(b[0]), "r"(b[1]));
}

static __device__ __forceinline__ void mma_bf16(float* c, const uint32_t* a,
                                                const uint32_t* b) {
    asm volatile(
        "mma.sync.aligned.m16n8k16.row.col.f32.bf16.bf16.f32 "
        "{%0,%1,%2,%3}, {%4,%5,%6,%7}, {%8,%9}, {%0,%1,%2,%3};"
        : "+f"(c[0]), "+f"(c[1]), "+f"(c[2]), "+f"(c[3])
        : "r"(a[0]), "r"(a[1]), "r"(a[2]), "r"(a[3]), "r"(b[0]), "r"(b[1]));
}

// bf16 hi/lo split (head path)
static __device__ __forceinline__ void split2(float x0, float x1, uint32_t& hi, uint32_t& lo) {
    __nv_bfloat16 h0 = __float2bfloat16(x0);
    __nv_bfloat16 h1 = __float2bfloat16(x1);
    __nv_bfloat16 l0 = __float2bfloat16(x0 - __bfloat162float(h0));
    __nv_bfloat16 l1 = __float2bfloat16(x1 - __bfloat162float(h1));
    __nv_bfloat162 hp; hp.x = h0; hp.y = h1;
    __nv_bfloat162 lp; lp.x = l0; lp.y = l1;
    hi = *(uint32_t*)&hp;
    lo = *(uint32_t*)&lp;
}

// ---------------------------------------------------------------------------
// conv: fp32 -> single fp16 plane, pre-swizzled. Tile = 128 rows x 64 k (16KB)
// (used for both x and W_enc)
// ---------------------------------------------------------------------------
__global__ void conv_f16_kernel(const float* __restrict__ S, unsigned char* __restrict__ D) {
    const int gid = blockIdx.x * 256 + threadIdx.x;
    const int n   = gid >> 8;
    const int k0  = (gid & 255) << 3;
    const float* src = S + (size_t)n * OBS_DIM + k0;
    float4 v0 = *(const float4*)src;
    float4 v1 = *(const float4*)(src + 4);
    float f[8] = {v0.x, v0.y, v0.z, v0.w, v1.x, v1.y, v1.z, v1.w};

    uint32_t hv[4];
#pragma unroll
    for (int j = 0; j < 4; j++) {
        __half2 hp;
        hp.x = __float2half_rn(f[2 * j]);
        hp.y = __float2half_rn(f[2 * j + 1]);
        hv[j] = *(uint32_t*)&hp;
    }

    const int c  = k0 >> 6;
    const int kl = k0 & 63;
    const int t  = n >> 7;
    const int nl = n & 127;
    const uint32_t byte = (uint32_t)nl * 128 +
                          (((uint32_t)kl * 2) ^ ((uint32_t)(nl & 7) << 4));
    unsigned char* blk = D + ((size_t)(t * NCHUNK + c)) * 16384;
    *(uint4*)(blk + byte) = make_uint4(hv[0], hv[1], hv[2], hv[3]);
}

// ---------------------------------------------------------------------------
// HMMA GEMM, 1-term fp16: relu(x @ W_enc^T + b_enc) -> g_Ahead (bf16 hi/lo)
// BN=256, 512 threads, 3-stage ring.
// ---------------------------------------------------------------------------
__global__ __launch_bounds__(512, 1) void enc_gemm_mma(const float* __restrict__ bias) {
    extern __shared__ __align__(1024) unsigned char smem[];
    const int tid = threadIdx.x;
    const int w = tid >> 5, l = tid & 31;
    const int mtile = blockIdx.x >> 1;
    const int ntile = blockIdx.x & 1;
    const int n0 = ntile * BN;
    const uint32_t sb = smem_addr_u32(smem);
    float* bsm = (float*)(smem + NSTAGE * STAGE);
    if (tid < 256) bsm[tid] = bias[n0 + tid];

    const unsigned char* gA = g_Astage + (size_t)mtile * NCHUNK * 16384;
    const unsigned char* gB0 = g_Bstage + (size_t)(ntile * 2) * NCHUNK * 16384;
    const unsigned char* gB1 = g_Bstage + (size_t)(ntile * 2 + 1) * NCHUNK * 16384;

    float acc[4][4][4];
#pragma unroll
    for (int i = 0; i < 4; i++)
#pragma unroll
        for (int j = 0; j < 4; j++)
#pragma unroll
            for (int q = 0; q < 4; q++) acc[i][j][q] = 0.f;

    const int wm = (w >> 3) * 64;
    const int wn = (w & 7) * 32;
    const int idx = l & 7, seg = l >> 3;
    const int arl = idx + (seg & 1) * 8;
    const int acb = (seg >> 1) * 16;
    const int brl = idx + (seg >> 1) * 8;
    const int bkb = (seg & 1) * 16;
    const uint32_t sxor = (uint32_t)idx << 4;

#define ISSUE(c, slot)                                                          \
    {                                                                           \
        const uint32_t dst = sb + (slot) * STAGE;                               \
        const unsigned char* ga  = gA  + (size_t)(c) * 16384;                   \
        const unsigned char* gb0 = gB0 + (size_t)(c) * 16384;                   \
        const unsigned char* gb1 = gB1 + (size_t)(c) * 16384;                   \
        _Pragma("unroll") for (int i = 0; i < 2; i++) {                         \
            uint32_t off = (uint32_t)(i * 512 + tid) * 16;                      \
            asm volatile("cp.async.cg.shared.global [%0], [%1], 16;"            \
                         :: "r"(dst + off), "l"(ga + off) : "memory");          \
            asm volatile("cp.async.cg.shared.global [%0], [%1], 16;"            \
                         :: "r"(dst + SB_OFF + off), "l"(gb0 + off) : "memory"); \
            asm volatile("cp.async.cg.shared.global [%0], [%1], 16;"            \
                         :: "r"(dst + SB_OFF + 16384 + off), "l"(gb1 + off) : "memory"); \
        }                                                                       \
        asm volatile("cp.async.commit_group;" ::: "memory");                    \
    }

    ISSUE(0, 0);
    ISSUE(1, 1);

    int slot = 0;
    for (int c = 0; c < NCHUNK; c++) {
        if (c + 2 < NCHUNK) {
            asm volatile("cp.async.wait_group 1;" ::: "memory");
        } else {
            asm volatile("cp.async.wait_group 0;" ::: "memory");
        }
        __syncthreads();

        if (c + 2 < NCHUNK) {
            const int ns = (slot + 2 >= NSTAGE) ? slot + 2 - NSTAGE : slot + 2;
            ISSUE(c + 2, ns);
        }

        const uint32_t stA = sb + slot * STAGE;
        const uint32_t stB = sb + slot * STAGE + SB_OFF;

#pragma unroll
        for (int ks = 0; ks < 4; ks++) {
            const int kb = ks * 32;
            uint32_t a[4][4], b[8];
#pragma unroll
            for (int mt = 0; mt < 4; mt++) {
                uint32_t off = (uint32_t)(wm + mt * 16 + arl) * 128 +
                               (((uint32_t)(kb + acb)) ^ sxor);
                ldm_x4(a[mt], stA + off);
            }
#pragma unroll
            for (int g = 0; g < 2; g++) {
                uint32_t off = (uint32_t)(wn + g * 16 + brl) * 128 +
                               (((uint32_t)(kb + bkb)) ^ sxor);
                ldm_x4(&b[g * 4], stB + off);
            }
#pragma unroll
            for (int mt = 0; mt < 4; mt++)
#pragma unroll
                for (int nt = 0; nt < 4; nt++)
                    mma_f16(acc[mt][nt], a[mt], &b[nt * 2]);
        }

        slot = (slot + 1 >= NSTAGE) ? 0 : slot + 1;
    }

    // epilogue: bias + relu, write as pre-swizzled hi/lo bf16 head tiles
    unsigned char* gAh = g_Ahead + (size_t)mtile * 8 * 32768;
#pragma unroll
    for (int mt = 0; mt < 4; mt++)
#pragma unroll
        for (int nt = 0; nt < 4; nt++) {
            const int colL = wn + nt * 8 + (l & 3) * 2;
            const float b0 = bsm[colL], b1 = bsm[colL + 1];
            const int rloc = wm + mt * 16 + (l >> 2);
            const int n = n0 + colL;
            const int cch = n >> 6;
            const int kc = n & 63;
            unsigned char* blk = gAh + (size_t)cch * 32768;

            float v0x = fmaxf(acc[mt][nt][0] + b0, 0.f);
            float v0y = fmaxf(acc[mt][nt][1] + b1, 0.f);
            float v1x = fmaxf(acc[mt][nt][2] + b0, 0.f);
            float v1y = fmaxf(acc[mt][nt][3] + b1, 0.f);

            uint32_t h01, l01, h23, l23;
            split2(v0x, v0y, h01, l01);
            split2(v1x, v1y, h23, l23);

            const uint32_t by0 = (uint32_t)rloc * 128 +
                                 (((uint32_t)(2 * kc)) ^ ((uint32_t)(rloc & 7) << 4));
            const int r1 = rloc + 8;
            const uint32_t by1 = (uint32_t)r1 * 128 +
                                 (((uint32_t)(2 * kc)) ^ ((uint32_t)(r1 & 7) << 4));
            *(uint32_t*)(blk + by0)         = h01;
            *(uint32_t*)(blk + 16384 + by0) = l01;
            *(uint32_t*)(blk + by1)         = h23;
            *(uint32_t*)(blk + 16384 + by1) = l23;
        }
}

// ---------------------------------------------------------------------------
// Head (R6-proven): per mtile HMMA [128 x 64 x 512] vs W'=[Ws;Wc;0pad],
// 3-term bf16 hi/lo, then per-agent serial softmax/entropy/value.
// ---------------------------------------------------------------------------
#define HB_H 0
#define HB_L 65536
#define HA   131072
#define HSTAGE 32768
#define HEAD_SMEM (HA + 2 * HSTAGE)  // 196608

__global__ __launch_bounds__(256, 1) void head_gemm_kernel(
    const float* __restrict__ Ws, const float* __restrict__ bs,
    const float* __restrict__ Wc, const float* __restrict__ bc,
    const int* __restrict__ skill, const int* __restrict__ action,
    float* __restrict__ out)
{
    extern __shared__ __align__(1024) unsigned char smem[];
    const int tid = threadIdx.x;
    const int w = tid >> 5, l = tid & 31;
    const int mtile = blockIdx.x;
    const uint32_t sb = smem_addr_u32(smem);

#pragma unroll
    for (int it = 0; it < 16; it++) {
        const int u = it * 256 + tid;
        const int row = u >> 6;
        const int k0 = (u & 63) << 3;
        float f[8];
        if (row < 32) {
            const float4* s4 = (const float4*)(Ws + (size_t)row * HID + k0);
            *(float4*)(f) = s4[0];
            *(float4*)(f + 4) = s4[1];
        } else if (row == 32) {
            const float4* s4 = (const float4*)(Wc + k0);
            *(float4*)(f) = s4[0];
            *(float4*)(f + 4) = s4[1];
        } else {
#pragma unroll
            for (int e = 0; e < 8; e++) f[e] = 0.f;
        }
        uint32_t hi[4], lo[4];
#pragma unroll
        for (int j = 0; j < 4; j++) split2(f[2 * j], f[2 * j + 1], hi[j], lo[j]);
        const int c = k0 >> 6;
        const int kl = k0 & 63;
        const uint32_t byte = (uint32_t)row * 128 +
                              (((uint32_t)kl * 2) ^ ((uint32_t)(row & 7) << 4));
        *(uint4*)(smem + HB_H + c * 8192 + byte) = make_uint4(hi[0], hi[1], hi[2], hi[3]);
        *(uint4*)(smem + HB_L + c * 8192 + byte) = make_uint4(lo[0], lo[1], lo[2], lo[3]);
    }

    const unsigned char* gA = g_Ahead + (size_t)mtile * 8 * 32768;

    float acc[2][4][4];
#pragma unroll
    for (int i = 0; i < 2; i++)
#pragma unroll
        for (int j = 0; j < 4; j++)
#pragma unroll
            for (int q = 0; q < 4; q++) acc[i][j][q] = 0.f;

    const int wm = (w >> 1) * 32;
    const int wn = (w & 1) * 32;
    const int idx = l & 7, seg = l >> 3;
    const int arl = idx + (seg & 1) * 8;
    const int acb = (seg >> 1) * 16;
    const int brl = idx + (seg >> 1) * 8;
    const int bkb = (seg & 1) * 16;
    const uint32_t sxor = (uint32_t)idx << 4;

#define HISSUE(c, slot)                                                        \
    {                                                                          \
        const uint32_t dst = sb + HA + (slot) * HSTAGE;                        \
        const unsigned char* ga = gA + (size_t)(c) * 32768;                    \
        _Pragma("unroll") for (int i = 0; i < 8; i++) {                        \
            uint32_t off = (uint32_t)(i * 256 + tid) * 16;                     \
            asm volatile("cp.async.cg.shared.global [%0], [%1], 16;"           \
                         :: "r"(dst + off), "l"(ga + off) : "memory");         \
        }                                                                      \
        asm volatile("cp.async.commit_group;" ::: "memory");                   \
    }

    HISSUE(0, 0);
    HISSUE(1, 1);
    __syncthreads();

    for (int c = 0; c < 8; c++) {
        const int slot = c & 1;
        if (c < 6) {
            asm volatile("cp.async.wait_group 1;" ::: "memory");
        } else {
            asm volatile("cp.async.wait_group 0;" ::: "memory");
        }
        __syncthreads();

        const uint32_t stA_hi = sb + HA + slot * HSTAGE;
        const uint32_t stA_lo = stA_hi + 16384;
        const uint32_t stB_hi = sb + HB_H + c * 8192;
        const uint32_t stB_lo = sb + HB_L + c * 8192;

#pragma unroll
        for (int ks = 0; ks < 4; ks++) {
            const int kb = ks * 32;
            uint32_t ah[2][4], al[2][4], bh[8], bl[8];
#pragma unroll
            for (int mt = 0; mt < 2; mt++) {
                uint32_t off = (uint32_t)(wm + mt * 16 + arl) * 128 +
                               (((uint32_t)(kb + acb)) ^ sxor);
                ldm_x4(ah[mt], stA_hi + off);
                ldm_x4(al[mt], stA_lo + off);
            }
#pragma unroll
            for (int g = 0; g < 2; g++) {
                uint32_t off = (uint32_t)(wn + g * 16 + brl) * 128 +
                               (((uint32_t)(kb + bkb)) ^ sxor);
                ldm_x4(&bh[g * 4], stB_hi + off);
                ldm_x4(&bl[g * 4], stB_lo + off);
            }
#pragma unroll
            for (int mt = 0; mt < 2; mt++)
#pragma unroll
                for (int nt = 0; nt < 4; nt++) {
                    mma_bf16(acc[mt][nt], ah[mt], &bh[nt * 2]);
                    mma_bf16(acc[mt][nt], ah[mt], &bl[nt * 2]);
                    mma_bf16(acc[mt][nt], al[mt], &bh[nt * 2]);
                }
        }

        __syncthreads();
        if (c + 2 < 8) HISSUE(c + 2, slot);
    }

    float* Lsm = (float*)(smem + HA);
#pragma unroll
    for (int mt = 0; mt < 2; mt++)
#pragma unroll
        for (int nt = 0; nt < 4; nt++) {
            const int colL = wn + nt * 8 + (l & 3) * 2;
            const int r0 = wm + mt * 16 + (l >> 2);
            *(float2*)(Lsm + r0 * 66 + colL)       = make_float2(acc[mt][nt][0], acc[mt][nt][1]);
            *(float2*)(Lsm + (r0 + 8) * 66 + colL) = make_float2(acc[mt][nt][2], acc[mt][nt][3]);
        }
    __syncthreads();

    if (tid < 128) {
        const int agent = mtile * 128 + tid;
        const float* Lr = Lsm + tid * 66;

        float lg[32];
        float mx = -1e30f;
#pragma unroll
        for (int t = 0; t < 32; t++) {
            lg[t] = Lr[t] + bs[t];
            mx = fmaxf(mx, lg[t]);
        }
        float se = 0.f, s1 = 0.f;
#pragma unroll
        for (int t = 0; t < 32; t++) {
            float e = expf(lg[t] - mx);
            se += e;
            s1 += e * lg[t];
        }
        const float lse = mx + logf(se);
        const int act = action[agent];
        const float slp = lg[act & 31] - lse;
        const float ent = lse - s1 / se;
        const float val = Lr[32] + bc[0];

        out[0 * N_AGENTS + agent] = (float)act;
        out[1 * N_AGENTS + agent] = (float)skill[agent];
        out[2 * N_AGENTS + agent] = -2.7725887222397811f;   // -ln(16)
        out[3 * N_AGENTS + agent] = slp;
        out[4 * N_AGENTS + agent] = ent;
        out[5 * N_AGENTS + agent] = val;
    }
}

// ---------------------------------------------------------------------------
// launch
// ---------------------------------------------------------------------------
extern "C" void kernel_launch(void* const* d_in, const int* in_sizes, int n_in,
                              void* d_out, int out_size) {
    (void)in_sizes; (void)n_in; (void)out_size;
    const float* x     = (const float*)d_in[0];
    const float* W_enc = (const float*)d_in[1];
    const float* b_enc = (const float*)d_in[2];
    // d_in[3]=Wm, d_in[4]=bm : dead (selections never returned)
    const float* Ws    = (const float*)d_in[5];
    const float* bs    = (const float*)d_in[6];
    const float* Wc    = (const float*)d_in[7];
    const float* bc    = (const float*)d_in[8];
    const int*   skill = (const int*)d_in[9];
    const int*   act   = (const int*)d_in[10];
    float* out = (float*)d_out;

    unsigned char* dA;
    cudaGetSymbolAddress((void**)&dA, g_Astage);
    unsigned char* dB;
    cudaGetSymbolAddress((void**)&dB, g_Bstage);

    static int cfg_done = 0;
    if (!cfg_done) {
        cudaFuncSetAttribute(enc_gemm_mma, cudaFuncAttributeMaxDynamicSharedMemorySize,
                             SMEM_TOTAL);
        cudaFuncSetAttribute(head_gemm_kernel, cudaFuncAttributeMaxDynamicSharedMemorySize,
                             HEAD_SMEM);
        cfg_done = 1;
    }

    conv_f16_kernel<<<512, 256>>>(W_enc, dB);             // 512 rows
    conv_f16_kernel<<<N_AGENTS, 256>>>(x, dA);            // 16384 rows

    enc_gemm_mma<<<NTILES * MTILES, 512, SMEM_TOTAL>>>(b_enc);

    head_gemm_kernel<<<MTILES, 256, HEAD_SMEM>>>(Ws, bs, Wc, bc, skill, act, out);
}

// round 11
// speedup vs baseline: 6.4959x; 1.1245x over previous
#include <cuda_runtime.h>
#include <cuda_bf16.h>
#include <cuda_fp16.h>
#include <stdint.h>

#define N_AGENTS 16384
#define OBS_DIM  2048
#define HID      512

// ---- enc GEMM tiling: BM=128, BN=256, KC=64, 512 threads, 1-term fp16,
//      fused in-smem fp32->fp16 conversion of x (thread-self-contained) ----
#define BM 128
#define BN 256
#define KC 64
#define NCHUNK (OBS_DIM / KC)    // 32
#define NTILES (HID / BN)        // 2
#define MTILES (N_AGENTS / BM)   // 128

// smem layout (bytes):
//   A32 ring : 3 x 32768  @ 0        (raw fp32 x chunk, linear rows of 256B)
//   A16 ring : 2 x 16384  @ 98304    (converted fp16, SW128 tile layout)
//   B   ring : 3 x 32768  @ 131072   (fp16 W tiles, SW128)
//   bias     : 1024       @ 229376
#define A32_OFF 0
#define A16_OFF 98304
#define B_OFF   131072
#define BIAS_OFF 229376
#define SMEM_TOTAL 230400

// B: pre-converted single fp16, [tile128][chunk][16K]
__device__ __align__(1024) unsigned char g_Bstage[(size_t)4 * NCHUNK * 16384];
// hidden, written by enc epilogue as pre-swizzled hi/lo bf16 head tiles:
// [mtile][hchunk 0..7][hi 16K | lo 16K]
__device__ __align__(1024) unsigned char g_Ahead[(size_t)MTILES * 8 * 32768];

static __device__ __forceinline__ uint32_t smem_addr_u32(const void* p) {
    uint32_t a;
    asm("{ .reg .u64 t; cvta.to.shared.u64 t, %1; cvt.u32.u64 %0, t; }" : "=r"(a) : "l"(p));
    return a;
}

static __device__ __forceinline__ void ldm_x4(uint32_t* r, uint32_t addr) {
    asm volatile("ldmatrix.sync.aligned.m8n8.x4.shared.b16 {%0,%1,%2,%3}, [%4];"
                 : "=r"(r[0]), "=r"(r[1]), "=r"(r[2]), "=r"(r[3]) : "r"(addr));
}

static __device__ __forceinline__ void mma_f16(float* c, const uint32_t* a,
                                               const uint32_t* b) {
    asm volatile(
        "mma.sync.aligned.m16n8k16.row.col.f32.f16.f16.f32 "
        "{%0,%1,%2,%3}, {%4,%5,%6,%7}, {%8,%9}, {%0,%1,%2,%3};"
        : "+f"(c[0]), "+f"(c[1]), "+f"(c[2]), "+f"(c[3])
        : "r"(a[0]), "r"(a[1]), "r"(a[2]), "r"(a[3]), "r"(b[0]), "r"(b[1]));
}

static __device__ __forceinline__ void mma_bf16(float* c, const uint32_t* a,
                                                const uint32_t* b) {
    asm volatile(
        "mma.sync.aligned.m16n8k16.row.col.f32.bf16.bf16.f32 "
        "{%0,%1,%2,%3}, {%4,%5,%6,%7}, {%8,%9}, {%0,%1,%2,%3};"
        : "+f"(c[0]), "+f"(c[1]), "+f"(c[2]), "+f"(c[3])
        : "r"(a[0]), "r"(a[1]), "r"(a[2]), "r"(a[3]), "r"(b[0]), "r"(b[1]));
}

// bf16 hi/lo split (head path)
static __device__ __forceinline__ void split2(float x0, float x1, uint32_t& hi, uint32_t& lo) {
    __nv_bfloat16 h0 = __float2bfloat16(x0);
    __nv_bfloat16 h1 = __float2bfloat16(x1);
    __nv_bfloat16 l0 = __float2bfloat16(x0 - __bfloat162float(h0));
    __nv_bfloat16 l1 = __float2bfloat16(x1 - __bfloat162float(h1));
    __nv_bfloat162 hp; hp.x = h0; hp.y = h1;
    __nv_bfloat162 lp; lp.x = l0; lp.y = l1;
    hi = *(uint32_t*)&hp;
    lo = *(uint32_t*)&lp;
}

static __device__ __forceinline__ uint32_t packh2(float x0, float x1) {
    __half2 hp;
    hp.x = __float2half_rn(x0);
    hp.y = __float2half_rn(x1);
    return *(uint32_t*)&hp;
}

// ---------------------------------------------------------------------------
// conv (W only): fp32 -> single fp16 plane, pre-swizzled.
// ---------------------------------------------------------------------------
__global__ void conv_f16_kernel(const float* __restrict__ S, unsigned char* __restrict__ D) {
    const int gid = blockIdx.x * 256 + threadIdx.x;
    const int n   = gid >> 8;
    const int k0  = (gid & 255) << 3;
    const float* src = S + (size_t)n * OBS_DIM + k0;
    float4 v0 = *(const float4*)src;
    float4 v1 = *(const float4*)(src + 4);

    uint32_t hv[4];
    hv[0] = packh2(v0.x, v0.y);
    hv[1] = packh2(v0.z, v0.w);
    hv[2] = packh2(v1.x, v1.y);
    hv[3] = packh2(v1.z, v1.w);

    const int c  = k0 >> 6;
    const int kl = k0 & 63;
    const int t  = n >> 7;
    const int nl = n & 127;
    const uint32_t byte = (uint32_t)nl * 128 +
                          (((uint32_t)kl * 2) ^ ((uint32_t)(nl & 7) << 4));
    unsigned char* blk = D + ((size_t)(t * NCHUNK + c)) * 16384;
    *(uint4*)(blk + byte) = make_uint4(hv[0], hv[1], hv[2], hv[3]);
}

// ---------------------------------------------------------------------------
// HMMA GEMM, 1-term fp16, fused x conversion (race-free: each thread converts
// exactly the bytes its own cp.asyncs delivered):
//   relu(x @ W_enc^T + b_enc) -> g_Ahead (bf16 hi/lo head tiles)
// ---------------------------------------------------------------------------
__global__ __launch_bounds__(512, 1) void enc_gemm_mma(
    const float* __restrict__ X, const float* __restrict__ bias)
{
    extern __shared__ __align__(1024) unsigned char smem[];
    const int tid = threadIdx.x;
    const int w = tid >> 5, l = tid & 31;
    const int mtile = blockIdx.x >> 1;
    const int ntile = blockIdx.x & 1;
    const int m0 = mtile * BM;
    const int n0 = ntile * BN;
    const uint32_t sb = smem_addr_u32(smem);
    float* bsm = (float*)(smem + BIAS_OFF);
    if (tid < 256) bsm[tid] = bias[n0 + tid];

    const float* gX = X + (size_t)m0 * OBS_DIM;
    const unsigned char* gB0 = g_Bstage + (size_t)(ntile * 2) * NCHUNK * 16384;
    const unsigned char* gB1 = g_Bstage + (size_t)(ntile * 2 + 1) * NCHUNK * 16384;

    float acc[4][4][4];
#pragma unroll
    for (int i = 0; i < 4; i++)
#pragma unroll
        for (int j = 0; j < 4; j++)
#pragma unroll
            for (int q = 0; q < 4; q++) acc[i][j][q] = 0.f;

    const int wm = (w >> 3) * 64;
    const int wn = (w & 7) * 32;
    const int idx = l & 7, seg = l >> 3;
    const int arl = idx + (seg & 1) * 8;
    const int acb = (seg >> 1) * 16;
    const int brl = idx + (seg >> 1) * 8;
    const int bkb = (seg & 1) * 16;
    const uint32_t sxor = (uint32_t)idx << 4;

    // one group per chunk: A32 (4x16B, blk = i*512+tid) + B (4x16B)
#define ISSUE(c, slot3)                                                         \
    {                                                                           \
        const uint32_t dstA = sb + A32_OFF + (slot3) * 32768;                   \
        const uint32_t dstB = sb + B_OFF + (slot3) * 32768;                     \
        const unsigned char* gb0 = gB0 + (size_t)(c) * 16384;                   \
        const unsigned char* gb1 = gB1 + (size_t)(c) * 16384;                   \
        _Pragma("unroll") for (int i = 0; i < 4; i++) {                         \
            const int blk = i * 512 + tid;                                      \
            const float* gsrc = gX + (size_t)(blk >> 4) * OBS_DIM +             \
                                (c) * KC + (blk & 15) * 4;                      \
            asm volatile("cp.async.cg.shared.global [%0], [%1], 16;"            \
                         :: "r"(dstA + (uint32_t)blk * 16), "l"(gsrc) : "memory"); \
        }                                                                       \
        _Pragma("unroll") for (int i = 0; i < 2; i++) {                         \
            uint32_t off = (uint32_t)(i * 512 + tid) * 16;                      \
            asm volatile("cp.async.cg.shared.global [%0], [%1], 16;"            \
                         :: "r"(dstB + off), "l"(gb0 + off) : "memory");        \
            asm volatile("cp.async.cg.shared.global [%0], [%1], 16;"            \
                         :: "r"(dstB + 16384 + off), "l"(gb1 + off) : "memory"); \
        }                                                                       \
        asm volatile("cp.async.commit_group;" ::: "memory");                    \
    }

    // Thread-self-contained convert: thread t reads the 4 x 16B blocks it
    // copied itself (blk = i*512+tid), converts, stores 8B swizzled to A16.
    // Guarded solely by this thread's cp.async.wait_group -> no cross-thread
    // dependency; A16 visibility to ldmatrix readers via next __syncthreads.
#define CONVERT(c)                                                              \
    {                                                                           \
        const int s3 = (c) % 3;                                                 \
        const int s2 = (c) & 1;                                                 \
        const unsigned char* a32 = smem + A32_OFF + s3 * 32768;                 \
        unsigned char* a16 = smem + A16_OFF + s2 * 16384;                       \
        _Pragma("unroll") for (int i = 0; i < 4; i++) {                         \
            const int blk = i * 512 + tid;                                      \
            float4 v = *(const float4*)(a32 + (size_t)blk * 16);                \
            uint32_t h0 = packh2(v.x, v.y);                                     \
            uint32_t h1 = packh2(v.z, v.w);                                     \
            const int row = blk >> 4;                                           \
            const uint32_t kb = (uint32_t)(blk & 15) * 8;                       \
            const uint32_t swo = (uint32_t)row * 128 +                          \
                                 (kb ^ ((uint32_t)(row & 7) << 4));             \
            *(uint2*)(a16 + swo) = make_uint2(h0, h1);                          \
        }                                                                       \
    }

    // prologue
    ISSUE(0, 0);
    ISSUE(1, 1);
    asm volatile("cp.async.wait_group 1;" ::: "memory");   // own group 0 done
    CONVERT(0);

    for (int c = 0; c < NCHUNK; c++) {
        __syncthreads();   // A16(c) + B(c) visible to all; slots (c-1)%3 free

        if (c + 2 < NCHUNK) {
            const int s3 = (c + 2) % 3;
            ISSUE(c + 2, s3);
        }

        const uint32_t stA = sb + A16_OFF + (c & 1) * 16384;
        const uint32_t stB = sb + B_OFF + (c % 3) * 32768;

#pragma unroll
        for (int ks = 0; ks < 4; ks++) {
            const int kb = ks * 32;
            uint32_t a[4][4], b[8];
#pragma unroll
            for (int mt = 0; mt < 4; mt++) {
                uint32_t off = (uint32_t)(wm + mt * 16 + arl) * 128 +
                               (((uint32_t)(kb + acb)) ^ sxor);
                ldm_x4(a[mt], stA + off);
            }
#pragma unroll
            for (int g = 0; g < 2; g++) {
                uint32_t off = (uint32_t)(wn + g * 16 + brl) * 128 +
                               (((uint32_t)(kb + bkb)) ^ sxor);
                ldm_x4(&b[g * 4], stB + off);
            }
#pragma unroll
            for (int mt = 0; mt < 4; mt++)
#pragma unroll
                for (int nt = 0; nt < 4; nt++)
                    mma_f16(acc[mt][nt], a[mt], &b[nt * 2]);
        }

        // convert next chunk (own cp.asyncs only; issued >=1 full iter ago)
        if (c + 1 < NCHUNK) {
            if (c + 2 < NCHUNK) {
                asm volatile("cp.async.wait_group 1;" ::: "memory");  // own c+1 done
            } else {
                asm volatile("cp.async.wait_group 0;" ::: "memory");
            }
            CONVERT(c + 1);
        }
    }

    // epilogue: bias + relu, write as pre-swizzled hi/lo bf16 head tiles
    unsigned char* gAh = g_Ahead + (size_t)mtile * 8 * 32768;
#pragma unroll
    for (int mt = 0; mt < 4; mt++)
#pragma unroll
        for (int nt = 0; nt < 4; nt++) {
            const int colL = wn + nt * 8 + (l & 3) * 2;
            const float b0 = bsm[colL], b1 = bsm[colL + 1];
            const int rloc = wm + mt * 16 + (l >> 2);
            const int n = n0 + colL;
            const int cch = n >> 6;
            const int kc = n & 63;
            unsigned char* blk = gAh + (size_t)cch * 32768;

            float v0x = fmaxf(acc[mt][nt][0] + b0, 0.f);
            float v0y = fmaxf(acc[mt][nt][1] + b1, 0.f);
            float v1x = fmaxf(acc[mt][nt][2] + b0, 0.f);
            float v1y = fmaxf(acc[mt][nt][3] + b1, 0.f);

            uint32_t h01, l01, h23, l23;
            split2(v0x, v0y, h01, l01);
            split2(v1x, v1y, h23, l23);

            const uint32_t by0 = (uint32_t)rloc * 128 +
                                 (((uint32_t)(2 * kc)) ^ ((uint32_t)(rloc & 7) << 4));
            const int r1 = rloc + 8;
            const uint32_t by1 = (uint32_t)r1 * 128 +
                                 (((uint32_t)(2 * kc)) ^ ((uint32_t)(r1 & 7) << 4));
            *(uint32_t*)(blk + by0)         = h01;
            *(uint32_t*)(blk + 16384 + by0) = l01;
            *(uint32_t*)(blk + by1)         = h23;
            *(uint32_t*)(blk + 16384 + by1) = l23;
        }
}

// ---------------------------------------------------------------------------
// Head (R6-proven): per mtile HMMA [128 x 64 x 512] vs W'=[Ws;Wc;0pad],
// 3-term bf16 hi/lo, then per-agent serial softmax/entropy/value.
// ---------------------------------------------------------------------------
#define HB_H 0
#define HB_L 65536
#define HA   131072
#define HSTAGE 32768
#define HEAD_SMEM (HA + 2 * HSTAGE)  // 196608

__global__ __launch_bounds__(256, 1) void head_gemm_kernel(
    const float* __restrict__ Ws, const float* __restrict__ bs,
    const float* __restrict__ Wc, const float* __restrict__ bc,
    const int* __restrict__ skill, const int* __restrict__ action,
    float* __restrict__ out)
{
    extern __shared__ __align__(1024) unsigned char smem[];
    const int tid = threadIdx.x;
    const int w = tid >> 5, l = tid & 31;
    const int mtile = blockIdx.x;
    const uint32_t sb = smem_addr_u32(smem);

#pragma unroll
    for (int it = 0; it < 16; it++) {
        const int u = it * 256 + tid;
        const int row = u >> 6;
        const int k0 = (u & 63) << 3;
        float f[8];
        if (row < 32) {
            const float4* s4 = (const float4*)(Ws + (size_t)row * HID + k0);
            *(float4*)(f) = s4[0];
            *(float4*)(f + 4) = s4[1];
        } else if (row == 32) {
            const float4* s4 = (const float4*)(Wc + k0);
            *(float4*)(f) = s4[0];
            *(float4*)(f + 4) = s4[1];
        } else {
#pragma unroll
            for (int e = 0; e < 8; e++) f[e] = 0.f;
        }
        uint32_t hi[4], lo[4];
#pragma unroll
        for (int j = 0; j < 4; j++) split2(f[2 * j], f[2 * j + 1], hi[j], lo[j]);
        const int c = k0 >> 6;
        const int kl = k0 & 63;
        const uint32_t byte = (uint32_t)row * 128 +
                              (((uint32_t)kl * 2) ^ ((uint32_t)(row & 7) << 4));
        *(uint4*)(smem + HB_H + c * 8192 + byte) = make_uint4(hi[0], hi[1], hi[2], hi[3]);
        *(uint4*)(smem + HB_L + c * 8192 + byte) = make_uint4(lo[0], lo[1], lo[2], lo[3]);
    }

    const unsigned char* gA = g_Ahead + (size_t)mtile * 8 * 32768;

    float acc[2][4][4];
#pragma unroll
    for (int i = 0; i < 2; i++)
#pragma unroll
        for (int j = 0; j < 4; j++)
#pragma unroll
            for (int q = 0; q < 4; q++) acc[i][j][q] = 0.f;

    const int wm = (w >> 1) * 32;
    const int wn = (w & 1) * 32;
    const int idx = l & 7, seg = l >> 3;
    const int arl = idx + (seg & 1) * 8;
    const int acb = (seg >> 1) * 16;
    const int brl = idx + (seg >> 1) * 8;
    const int bkb = (seg & 1) * 16;
    const uint32_t sxor = (uint32_t)idx << 4;

#define HISSUE(c, slot)                                                        \
    {                                                                          \
        const uint32_t dst = sb + HA + (slot) * HSTAGE;                        \
        const unsigned char* ga = gA + (size_t)(c) * 32768;                    \
        _Pragma("unroll") for (int i = 0; i < 8; i++) {                        \
            uint32_t off = (uint32_t)(i * 256 + tid) * 16;                     \
            asm volatile("cp.async.cg.shared.global [%0], [%1], 16;"           \
                         :: "r"(dst + off), "l"(ga + off) : "memory");         \
        }                                                                      \
        asm volatile("cp.async.commit_group;" ::: "memory");                   \
    }

    HISSUE(0, 0);
    HISSUE(1, 1);
    __syncthreads();

    for (int c = 0; c < 8; c++) {
        const int slot = c & 1;
        if (c < 6) {
            asm volatile("cp.async.wait_group 1;" ::: "memory");
        } else {
            asm volatile("cp.async.wait_group 0;" ::: "memory");
        }
        __syncthreads();

        const uint32_t stA_hi = sb + HA + slot * HSTAGE;
        const uint32_t stA_lo = stA_hi + 16384;
        const uint32_t stB_hi = sb + HB_H + c * 8192;
        const uint32_t stB_lo = sb + HB_L + c * 8192;

#pragma unroll
        for (int ks = 0; ks < 4; ks++) {
            const int kb = ks * 32;
            uint32_t ah[2][4], al[2][4], bh[8], bl[8];
#pragma unroll
            for (int mt = 0; mt < 2; mt++) {
                uint32_t off = (uint32_t)(wm + mt * 16 + arl) * 128 +
                               (((uint32_t)(kb + acb)) ^ sxor);
                ldm_x4(ah[mt], stA_hi + off);
                ldm_x4(al[mt], stA_lo + off);
            }
#pragma unroll
            for (int g = 0; g < 2; g++) {
                uint32_t off = (uint32_t)(wn + g * 16 + brl) * 128 +
                               (((uint32_t)(kb + bkb)) ^ sxor);
                ldm_x4(&bh[g * 4], stB_hi + off);
                ldm_x4(&bl[g * 4], stB_lo + off);
            }
#pragma unroll
            for (int mt = 0; mt < 2; mt++)
#pragma unroll
                for (int nt = 0; nt < 4; nt++) {
                    mma_bf16(acc[mt][nt], ah[mt], &bh[nt * 2]);
                    mma_bf16(acc[mt][nt], ah[mt], &bl[nt * 2]);
                    mma_bf16(acc[mt][nt], al[mt], &bh[nt * 2]);
                }
        }

        __syncthreads();
        if (c + 2 < 8) HISSUE(c + 2, slot);
    }

    float* Lsm = (float*)(smem + HA);
#pragma unroll
    for (int mt = 0; mt < 2; mt++)
#pragma unroll
        for (int nt = 0; nt < 4; nt++) {
            const int colL = wn + nt * 8 + (l & 3) * 2;
            const int r0 = wm + mt * 16 + (l >> 2);
            *(float2*)(Lsm + r0 * 66 + colL)       = make_float2(acc[mt][nt][0], acc[mt][nt][1]);
            *(float2*)(Lsm + (r0 + 8) * 66 + colL) = make_float2(acc[mt][nt][2], acc[mt][nt][3]);
        }
    __syncthreads();

    if (tid < 128) {
        const int agent = mtile * 128 + tid;
        const float* Lr = Lsm + tid * 66;

        float lg[32];
        float mx = -1e30f;
#pragma unroll
        for (int t = 0; t < 32; t++) {
            lg[t] = Lr[t] + bs[t];
            mx = fmaxf(mx, lg[t]);
        }
        float se = 0.f, s1 = 0.f;
#pragma unroll
        for (int t = 0; t < 32; t++) {
            float e = expf(lg[t] - mx);
            se += e;
            s1 += e * lg[t];
        }
        const float lse = mx + logf(se);
        const int act = action[agent];
        const float slp = lg[act & 31] - lse;
        const float ent = lse - s1 / se;
        const float val = Lr[32] + bc[0];

        out[0 * N_AGENTS + agent] = (float)act;
        out[1 * N_AGENTS + agent] = (float)skill[agent];
        out[2 * N_AGENTS + agent] = -2.7725887222397811f;   // -ln(16)
        out[3 * N_AGENTS + agent] = slp;
        out[4 * N_AGENTS + agent] = ent;
        out[5 * N_AGENTS + agent] = val;
    }
}

// ---------------------------------------------------------------------------
// launch
// ---------------------------------------------------------------------------
extern "C" void kernel_launch(void* const* d_in, const int* in_sizes, int n_in,
                              void* d_out, int out_size) {
    (void)in_sizes; (void)n_in; (void)out_size;
    const float* x     = (const float*)d_in[0];
    const float* W_enc = (const float*)d_in[1];
    const float* b_enc = (const float*)d_in[2];
    // d_in[3]=Wm, d_in[4]=bm : dead (selections never returned)
    const float* Ws    = (const float*)d_in[5];
    const float* bs    = (const float*)d_in[6];
    const float* Wc    = (const float*)d_in[7];
    const float* bc    = (const float*)d_in[8];
    const int*   skill = (const int*)d_in[9];
    const int*   act   = (const int*)d_in[10];
    float* out = (float*)d_out;

    unsigned char* dB;
    cudaGetSymbolAddress((void**)&dB, g_Bstage);

    static int cfg_done = 0;
    if (!cfg_done) {
        cudaFuncSetAttribute(enc_gemm_mma, cudaFuncAttributeMaxDynamicSharedMemorySize,
                             SMEM_TOTAL);
        cudaFuncSetAttribute(head_gemm_kernel, cudaFuncAttributeMaxDynamicSharedMemorySize,
                             HEAD_SMEM);
        cfg_done = 1;
    }

    conv_f16_kernel<<<512, 256>>>(W_enc, dB);             // W only (512 rows)

    enc_gemm_mma<<<NTILES * MTILES, 512, SMEM_TOTAL>>>(x, b_enc);

    head_gemm_kernel<<<MTILES, 256, HEAD_SMEM>>>(Ws, bs, Wc, bc, skill, act, out);
}

// round 12
// speedup vs baseline: 6.9414x; 1.0686x over previous
#include <cuda_runtime.h>
#include <cuda_bf16.h>
#include <cuda_fp16.h>
#include <stdint.h>

#define N_AGENTS 16384
#define OBS_DIM  2048
#define HID      512

// ---- enc GEMM tiling: BM=128, BN=256, KC=64, 512 threads, 1-term fp16,
//      fused in-smem fp32->fp16 conversion of x (thread-self-contained) ----
#define BM 128
#define BN 256
#define KC 64
#define NCHUNK (OBS_DIM / KC)    // 32
#define NTILES (HID / BN)        // 2
#define MTILES (N_AGENTS / BM)   // 128

// enc smem layout (bytes):
//   A32 ring : 3 x 32768  @ 0
//   A16 ring : 2 x 16384  @ 98304
//   B   ring : 3 x 32768  @ 131072
//   bias     : 1024       @ 229376
#define A32_OFF 0
#define A16_OFF 98304
#define B_OFF   131072
#define BIAS_OFF 229376
#define SMEM_TOTAL 230400

// B: pre-converted single fp16, [tile128][chunk][16K]
__device__ __align__(1024) unsigned char g_Bstage[(size_t)4 * NCHUNK * 16384];
// hidden: single fp16 plane head tiles: [mtile][hchunk 0..7][16K]
__device__ __align__(1024) unsigned char g_Ahead[(size_t)MTILES * 8 * 16384];
// W' = [Ws(32); Wc(1); 0(31)] fp16 hi/lo: [chunk 0..7][hi 8K | lo 8K]
__device__ __align__(1024) unsigned char g_Whead[(size_t)8 * 16384];

static __device__ __forceinline__ uint32_t smem_addr_u32(const void* p) {
    uint32_t a;
    asm("{ .reg .u64 t; cvta.to.shared.u64 t, %1; cvt.u32.u64 %0, t; }" : "=r"(a) : "l"(p));
    return a;
}

static __device__ __forceinline__ void ldm_x4(uint32_t* r, uint32_t addr) {
    asm volatile("ldmatrix.sync.aligned.m8n8.x4.shared.b16 {%0,%1,%2,%3}, [%4];"
                 : "=r"(r[0]), "=r"(r[1]), "=r"(r[2]), "=r"(r[3]) : "r"(addr));
}

static __device__ __forceinline__ void mma_f16(float* c, const uint32_t* a,
                                               const uint32_t* b) {
    asm volatile(
        "mma.sync.aligned.m16n8k16.row.col.f32.f16.f16.f32 "
        "{%0,%1,%2,%3}, {%4,%5,%6,%7}, {%8,%9}, {%0,%1,%2,%3};"
        : "+f"(c[0]), "+f"(c[1]), "+f"(c[2]), "+f"(c[3])
        : "r"(a[0]), "r"(a[1]), "r"(a[2]), "r"(a[3]), "r"(b[0]), "r"(b[1]));
}

static __device__ __forceinline__ uint32_t packh2(float x0, float x1) {
    __half2 hp;
    hp.x = __float2half_rn(x0);
    hp.y = __float2half_rn(x1);
    return *(uint32_t*)&hp;
}

// fp16 hi/lo split (head W' path)
static __device__ __forceinline__ void split2h(float x0, float x1, uint32_t& hi, uint32_t& lo) {
    __half h0 = __float2half_rn(x0);
    __half h1 = __float2half_rn(x1);
    __half l0 = __float2half_rn(x0 - __half2float(h0));
    __half l1 = __float2half_rn(x1 - __half2float(h1));
    __half2 hp; hp.x = h0; hp.y = h1;
    __half2 lp; lp.x = l0; lp.y = l1;
    hi = *(uint32_t*)&hp;
    lo = *(uint32_t*)&lp;
}

// ---------------------------------------------------------------------------
// conv (W_enc): fp32 -> single fp16 plane, pre-swizzled.
// ---------------------------------------------------------------------------
__global__ void conv_f16_kernel(const float* __restrict__ S, unsigned char* __restrict__ D) {
    const int gid = blockIdx.x * 256 + threadIdx.x;
    const int n   = gid >> 8;
    const int k0  = (gid & 255) << 3;
    const float* src = S + (size_t)n * OBS_DIM + k0;
    float4 v0 = *(const float4*)src;
    float4 v1 = *(const float4*)(src + 4);

    uint32_t hv[4];
    hv[0] = packh2(v0.x, v0.y);
    hv[1] = packh2(v0.z, v0.w);
    hv[2] = packh2(v1.x, v1.y);
    hv[3] = packh2(v1.z, v1.w);

    const int c  = k0 >> 6;
    const int kl = k0 & 63;
    const int t  = n >> 7;
    const int nl = n & 127;
    const uint32_t byte = (uint32_t)nl * 128 +
                          (((uint32_t)kl * 2) ^ ((uint32_t)(nl & 7) << 4));
    unsigned char* blk = D + ((size_t)(t * NCHUNK + c)) * 16384;
    *(uint4*)(blk + byte) = make_uint4(hv[0], hv[1], hv[2], hv[3]);
}

// ---------------------------------------------------------------------------
// conv W' (head B): [Ws(32); Wc(1); 0(31)] fp32[64x512] -> fp16 hi/lo,
// pre-swizzled 64-row x 64-col chunks: g_Whead[c][hi 8K | lo 8K].
// grid 16 x 256 (4096 units of 8 floats)
// ---------------------------------------------------------------------------
__global__ void conv_wh_kernel(const float* __restrict__ Ws, const float* __restrict__ Wc) {
    const int u   = blockIdx.x * 256 + threadIdx.x;   // 0..4095
    const int row = u >> 6;                            // 0..63
    const int k0  = (u & 63) << 3;                     // 0..504 step 8
    float f[8];
    if (row < 32) {
        const float4* s4 = (const float4*)(Ws + (size_t)row * HID + k0);
        *(float4*)(f) = s4[0];
        *(float4*)(f + 4) = s4[1];
    } else if (row == 32) {
        const float4* s4 = (const float4*)(Wc + k0);
        *(float4*)(f) = s4[0];
        *(float4*)(f + 4) = s4[1];
    } else {
#pragma unroll
        for (int e = 0; e < 8; e++) f[e] = 0.f;
    }
    uint32_t hi[4], lo[4];
#pragma unroll
    for (int j = 0; j < 4; j++) split2h(f[2 * j], f[2 * j + 1], hi[j], lo[j]);
    const int c  = k0 >> 6;
    const int kl = k0 & 63;
    const uint32_t byte = (uint32_t)row * 128 +
                          (((uint32_t)kl * 2) ^ ((uint32_t)(row & 7) << 4));
    unsigned char* blk = g_Whead + (size_t)c * 16384;
    *(uint4*)(blk + byte)        = make_uint4(hi[0], hi[1], hi[2], hi[3]);
    *(uint4*)(blk + 8192 + byte) = make_uint4(lo[0], lo[1], lo[2], lo[3]);
}

// ---------------------------------------------------------------------------
// HMMA GEMM, 1-term fp16, fused x conversion (R11-proven schedule):
//   relu(x @ W_enc^T + b_enc) -> g_Ahead (single fp16 plane head tiles)
// ---------------------------------------------------------------------------
__global__ __launch_bounds__(512, 1) void enc_gemm_mma(
    const float* __restrict__ X, const float* __restrict__ bias)
{
    extern __shared__ __align__(1024) unsigned char smem[];
    const int tid = threadIdx.x;
    const int w = tid >> 5, l = tid & 31;
    const int mtile = blockIdx.x >> 1;
    const int ntile = blockIdx.x & 1;
    const int m0 = mtile * BM;
    const int n0 = ntile * BN;
    const uint32_t sb = smem_addr_u32(smem);
    float* bsm = (float*)(smem + BIAS_OFF);
    if (tid < 256) bsm[tid] = bias[n0 + tid];

    const float* gX = X + (size_t)m0 * OBS_DIM;
    const unsigned char* gB0 = g_Bstage + (size_t)(ntile * 2) * NCHUNK * 16384;
    const unsigned char* gB1 = g_Bstage + (size_t)(ntile * 2 + 1) * NCHUNK * 16384;

    float acc[4][4][4];
#pragma unroll
    for (int i = 0; i < 4; i++)
#pragma unroll
        for (int j = 0; j < 4; j++)
#pragma unroll
            for (int q = 0; q < 4; q++) acc[i][j][q] = 0.f;

    const int wm = (w >> 3) * 64;
    const int wn = (w & 7) * 32;
    const int idx = l & 7, seg = l >> 3;
    const int arl = idx + (seg & 1) * 8;
    const int acb = (seg >> 1) * 16;
    const int brl = idx + (seg >> 1) * 8;
    const int bkb = (seg & 1) * 16;
    const uint32_t sxor = (uint32_t)idx << 4;

#define ISSUE(c, slot3)                                                         \
    {                                                                           \
        const uint32_t dstA = sb + A32_OFF + (slot3) * 32768;                   \
        const uint32_t dstB = sb + B_OFF + (slot3) * 32768;                     \
        const unsigned char* gb0 = gB0 + (size_t)(c) * 16384;                   \
        const unsigned char* gb1 = gB1 + (size_t)(c) * 16384;                   \
        _Pragma("unroll") for (int i = 0; i < 4; i++) {                         \
            const int blk = i * 512 + tid;                                      \
            const float* gsrc = gX + (size_t)(blk >> 4) * OBS_DIM +             \
                                (c) * KC + (blk & 15) * 4;                      \
            asm volatile("cp.async.cg.shared.global [%0], [%1], 16;"            \
                         :: "r"(dstA + (uint32_t)blk * 16), "l"(gsrc) : "memory"); \
        }                                                                       \
        _Pragma("unroll") for (int i = 0; i < 2; i++) {                         \
            uint32_t off = (uint32_t)(i * 512 + tid) * 16;                      \
            asm volatile("cp.async.cg.shared.global [%0], [%1], 16;"            \
                         :: "r"(dstB + off), "l"(gb0 + off) : "memory");        \
            asm volatile("cp.async.cg.shared.global [%0], [%1], 16;"            \
                         :: "r"(dstB + 16384 + off), "l"(gb1 + off) : "memory"); \
        }                                                                       \
        asm volatile("cp.async.commit_group;" ::: "memory");                    \
    }

#define CONVERT(c)                                                              \
    {                                                                           \
        const int s3 = (c) % 3;                                                 \
        const int s2 = (c) & 1;                                                 \
        const unsigned char* a32 = smem + A32_OFF + s3 * 32768;                 \
        unsigned char* a16 = smem + A16_OFF + s2 * 16384;                       \
        _Pragma("unroll") for (int i = 0; i < 4; i++) {                         \
            const int blk = i * 512 + tid;                                      \
            float4 v = *(const float4*)(a32 + (size_t)blk * 16);                \
            uint32_t h0 = packh2(v.x, v.y);                                     \
            uint32_t h1 = packh2(v.z, v.w);                                     \
            const int row = blk >> 4;                                           \
            const uint32_t kb = (uint32_t)(blk & 15) * 8;                       \
            const uint32_t swo = (uint32_t)row * 128 +                          \
                                 (kb ^ ((uint32_t)(row & 7) << 4));             \
            *(uint2*)(a16 + swo) = make_uint2(h0, h1);                          \
        }                                                                       \
    }

    // prologue
    ISSUE(0, 0);
    ISSUE(1, 1);
    asm volatile("cp.async.wait_group 1;" ::: "memory");
    CONVERT(0);

    for (int c = 0; c < NCHUNK; c++) {
        __syncthreads();

        if (c + 2 < NCHUNK) {
            const int s3 = (c + 2) % 3;
            ISSUE(c + 2, s3);
        }

        const uint32_t stA = sb + A16_OFF + (c & 1) * 16384;
        const uint32_t stB = sb + B_OFF + (c % 3) * 32768;

#pragma unroll
        for (int ks = 0; ks < 4; ks++) {
            const int kb = ks * 32;
            uint32_t a[4][4], b[8];
#pragma unroll
            for (int mt = 0; mt < 4; mt++) {
                uint32_t off = (uint32_t)(wm + mt * 16 + arl) * 128 +
                               (((uint32_t)(kb + acb)) ^ sxor);
                ldm_x4(a[mt], stA + off);
            }
#pragma unroll
            for (int g = 0; g < 2; g++) {
                uint32_t off = (uint32_t)(wn + g * 16 + brl) * 128 +
                               (((uint32_t)(kb + bkb)) ^ sxor);
                ldm_x4(&b[g * 4], stB + off);
            }
#pragma unroll
            for (int mt = 0; mt < 4; mt++)
#pragma unroll
                for (int nt = 0; nt < 4; nt++)
                    mma_f16(acc[mt][nt], a[mt], &b[nt * 2]);
        }

        if (c + 1 < NCHUNK) {
            if (c + 2 < NCHUNK) {
                asm volatile("cp.async.wait_group 1;" ::: "memory");
            } else {
                asm volatile("cp.async.wait_group 0;" ::: "memory");
            }
            CONVERT(c + 1);
        }
    }

    // epilogue: bias + relu, write single fp16 plane head tiles
    unsigned char* gAh = g_Ahead + (size_t)mtile * 8 * 16384;
#pragma unroll
    for (int mt = 0; mt < 4; mt++)
#pragma unroll
        for (int nt = 0; nt < 4; nt++) {
            const int colL = wn + nt * 8 + (l & 3) * 2;
            const float b0 = bsm[colL], b1 = bsm[colL + 1];
            const int rloc = wm + mt * 16 + (l >> 2);
            const int n = n0 + colL;
            const int cch = n >> 6;
            const int kc = n & 63;
            unsigned char* blk = gAh + (size_t)cch * 16384;

            const uint32_t h01 = packh2(fmaxf(acc[mt][nt][0] + b0, 0.f),
                                        fmaxf(acc[mt][nt][1] + b1, 0.f));
            const uint32_t h23 = packh2(fmaxf(acc[mt][nt][2] + b0, 0.f),
                                        fmaxf(acc[mt][nt][3] + b1, 0.f));

            const uint32_t by0 = (uint32_t)rloc * 128 +
                                 (((uint32_t)(2 * kc)) ^ ((uint32_t)(rloc & 7) << 4));
            const int r1 = rloc + 8;
            const uint32_t by1 = (uint32_t)r1 * 128 +
                                 (((uint32_t)(2 * kc)) ^ ((uint32_t)(r1 & 7) << 4));
            *(uint32_t*)(blk + by0) = h01;
            *(uint32_t*)(blk + by1) = h23;
        }
}

// ---------------------------------------------------------------------------
// Head v2: per mtile, HMMA [128 x 64 x 512], A = fp16 hidden (4-deep ring),
// B = W' fp16 hi/lo (whole 128KB staged once), 2-term. Then softmax etc.
// smem: HB 8 x 16K @0 ; HA ring 4 x 16K @131072 ; logits reuse @0.
// ---------------------------------------------------------------------------
#define HB_OFF 0
#define HA_OFF 131072
#define HEAD_SMEM 196608

__global__ __launch_bounds__(256, 1) void head_gemm_kernel(
    const float* __restrict__ bs, const float* __restrict__ bc,
    const int* __restrict__ skill, const int* __restrict__ action,
    float* __restrict__ out)
{
    extern __shared__ __align__(1024) unsigned char smem[];
    const int tid = threadIdx.x;
    const int w = tid >> 5, l = tid & 31;
    const int mtile = blockIdx.x;
    const uint32_t sb = smem_addr_u32(smem);

    const unsigned char* gA = g_Ahead + (size_t)mtile * 8 * 16384;

    // group 0: whole W' (128KB), 32 x 16B per thread
    {
        const uint32_t dst = sb + HB_OFF;
#pragma unroll
        for (int i = 0; i < 32; i++) {
            uint32_t off = (uint32_t)(i * 256 + tid) * 16;
            asm volatile("cp.async.cg.shared.global [%0], [%1], 16;"
                         :: "r"(dst + off), "l"(g_Whead + off) : "memory");
        }
        asm volatile("cp.async.commit_group;" ::: "memory");
    }

#define HISSUE(c)                                                              \
    {                                                                          \
        const uint32_t dst = sb + HA_OFF + ((c) & 3) * 16384;                  \
        const unsigned char* ga = gA + (size_t)(c) * 16384;                    \
        _Pragma("unroll") for (int i = 0; i < 4; i++) {                        \
            uint32_t off = (uint32_t)(i * 256 + tid) * 16;                     \
            asm volatile("cp.async.cg.shared.global [%0], [%1], 16;"           \
                         :: "r"(dst + off), "l"(ga + off) : "memory");         \
        }                                                                      \
        asm volatile("cp.async.commit_group;" ::: "memory");                   \
    }

    HISSUE(0);
    HISSUE(1);
    HISSUE(2);

    float acc[2][4][4];
#pragma unroll
    for (int i = 0; i < 2; i++)
#pragma unroll
        for (int j = 0; j < 4; j++)
#pragma unroll
            for (int q = 0; q < 4; q++) acc[i][j][q] = 0.f;

    const int wm = (w >> 1) * 32;
    const int wn = (w & 1) * 32;
    const int idx = l & 7, seg = l >> 3;
    const int arl = idx + (seg & 1) * 8;
    const int acb = (seg >> 1) * 16;
    const int brl = idx + (seg >> 1) * 8;
    const int bkb = (seg & 1) * 16;
    const uint32_t sxor = (uint32_t)idx << 4;

    for (int c = 0; c < 8; c++) {
        // need W' + A_c complete; younger groups: A_{c+1}, A_{c+2} (if issued)
        if (c <= 5) {
            asm volatile("cp.async.wait_group 2;" ::: "memory");
        } else if (c == 6) {
            asm volatile("cp.async.wait_group 1;" ::: "memory");
        } else {
            asm volatile("cp.async.wait_group 0;" ::: "memory");
        }
        __syncthreads();   // chunk c visible to all; slot (c+3)&3 = (c-1)&3 free

        if (c + 3 < 8) HISSUE(c + 3);

        const uint32_t stA    = sb + HA_OFF + (c & 3) * 16384;
        const uint32_t stB_hi = sb + HB_OFF + c * 16384;
        const uint32_t stB_lo = stB_hi + 8192;

#pragma unroll
        for (int ks = 0; ks < 4; ks++) {
            const int kb = ks * 32;
            uint32_t a[2][4], bh[8], bl[8];
#pragma unroll
            for (int mt = 0; mt < 2; mt++) {
                uint32_t off = (uint32_t)(wm + mt * 16 + arl) * 128 +
                               (((uint32_t)(kb + acb)) ^ sxor);
                ldm_x4(a[mt], stA + off);
            }
#pragma unroll
            for (int g = 0; g < 2; g++) {
                uint32_t off = (uint32_t)(wn + g * 16 + brl) * 128 +
                               (((uint32_t)(kb + bkb)) ^ sxor);
                ldm_x4(&bh[g * 4], stB_hi + off);
                ldm_x4(&bl[g * 4], stB_lo + off);
            }
#pragma unroll
            for (int mt = 0; mt < 2; mt++)
#pragma unroll
                for (int nt = 0; nt < 4; nt++) {
                    mma_f16(acc[mt][nt], a[mt], &bh[nt * 2]);
                    mma_f16(acc[mt][nt], a[mt], &bl[nt * 2]);
                }
        }
    }

    __syncthreads();   // all MMAs done before logits overwrite HB region

    float* Lsm = (float*)(smem + HB_OFF);    // [128][66]
#pragma unroll
    for (int mt = 0; mt < 2; mt++)
#pragma unroll
        for (int nt = 0; nt < 4; nt++) {
            const int colL = wn + nt * 8 + (l & 3) * 2;
            const int r0 = wm + mt * 16 + (l >> 2);
            *(float2*)(Lsm + r0 * 66 + colL)       = make_float2(acc[mt][nt][0], acc[mt][nt][1]);
            *(float2*)(Lsm + (r0 + 8) * 66 + colL) = make_float2(acc[mt][nt][2], acc[mt][nt][3]);
        }
    __syncthreads();

    if (tid < 128) {
        const int agent = mtile * 128 + tid;
        const float* Lr = Lsm + tid * 66;

        float lg[32];
        float mx = -1e30f;
#pragma unroll
        for (int t = 0; t < 32; t++) {
            lg[t] = Lr[t] + bs[t];
            mx = fmaxf(mx, lg[t]);
        }
        float se = 0.f, s1 = 0.f;
#pragma unroll
        for (int t = 0; t < 32; t++) {
            float e = expf(lg[t] - mx);
            se += e;
            s1 += e * lg[t];
        }
        const float lse = mx + logf(se);
        const int act = action[agent];
        const float slp = lg[act & 31] - lse;
        const float ent = lse - s1 / se;
        const float val = Lr[32] + bc[0];

        out[0 * N_AGENTS + agent] = (float)act;
        out[1 * N_AGENTS + agent] = (float)skill[agent];
        out[2 * N_AGENTS + agent] = -2.7725887222397811f;   // -ln(16)
        out[3 * N_AGENTS + agent] = slp;
        out[4 * N_AGENTS + agent] = ent;
        out[5 * N_AGENTS + agent] = val;
    }
}

// ---------------------------------------------------------------------------
// launch
// ---------------------------------------------------------------------------
extern "C" void kernel_launch(void* const* d_in, const int* in_sizes, int n_in,
                              void* d_out, int out_size) {
    (void)in_sizes; (void)n_in; (void)out_size;
    const float* x     = (const float*)d_in[0];
    const float* W_enc = (const float*)d_in[1];
    const float* b_enc = (const float*)d_in[2];
    // d_in[3]=Wm, d_in[4]=bm : dead (selections never returned)
    const float* Ws    = (const float*)d_in[5];
    const float* bs    = (const float*)d_in[6];
    const float* Wc    = (const float*)d_in[7];
    const float* bc    = (const float*)d_in[8];
    const int*   skill = (const int*)d_in[9];
    const int*   act   = (const int*)d_in[10];
    float* out = (float*)d_out;

    unsigned char* dB;
    cudaGetSymbolAddress((void**)&dB, g_Bstage);

    static int cfg_done = 0;
    if (!cfg_done) {
        cudaFuncSetAttribute(enc_gemm_mma, cudaFuncAttributeMaxDynamicSharedMemorySize,
                             SMEM_TOTAL);
        cudaFuncSetAttribute(head_gemm_kernel, cudaFuncAttributeMaxDynamicSharedMemorySize,
                             HEAD_SMEM);
        cfg_done = 1;
    }

    conv_f16_kernel<<<512, 256>>>(W_enc, dB);   // W_enc -> fp16 tiles
    conv_wh_kernel<<<16, 256>>>(Ws, Wc);        // W' -> fp16 hi/lo staging

    enc_gemm_mma<<<NTILES * MTILES, 512, SMEM_TOTAL>>>(x, b_enc);

    head_gemm_kernel<<<MTILES, 256, HEAD_SMEM>>>(bs, bc, skill, act, out);
}

// round 14
// speedup vs baseline: 7.0368x; 1.0137x over previous
#include <cuda_runtime.h>
#include <cuda_bf16.h>
#include <cuda_fp16.h>
#include <stdint.h>

#define N_AGENTS 16384
#define OBS_DIM  2048
#define HID      512

// ---- enc GEMM tiling: BM=128, BN=256, KC=64, 512 threads, 1-term fp16,
//      fused in-smem fp32->fp16 conversion of x (R11/R12-proven) ----
#define BM 128
#define BN 256
#define KC 64
#define NCHUNK (OBS_DIM / KC)    // 32
#define NTILES (HID / BN)        // 2
#define MTILES (N_AGENTS / BM)   // 128

#define A32_OFF 0
#define A16_OFF 98304
#define B_OFF   131072
#define BIAS_OFF 229376
#define SMEM_TOTAL 230400

// B: pre-converted single fp16, [tile128][chunk][16K]
__device__ __align__(1024) unsigned char g_Bstage[(size_t)4 * NCHUNK * 16384];
// hidden: single fp16 plane head tiles: [mtile][hchunk 0..7][16K]
__device__ __align__(1024) unsigned char g_Ahead[(size_t)MTILES * 8 * 16384];
// W' = [Ws(32); Wc(1); 0(31)] single fp16: [chunk 0..7][8K]
__device__ __align__(1024) unsigned char g_Whead[(size_t)8 * 8192];

static __device__ __forceinline__ uint32_t smem_addr_u32(const void* p) {
    uint32_t a;
    asm("{ .reg .u64 t; cvta.to.shared.u64 t, %1; cvt.u32.u64 %0, t; }" : "=r"(a) : "l"(p));
    return a;
}

static __device__ __forceinline__ void ldm_x4(uint32_t* r, uint32_t addr) {
    asm volatile("ldmatrix.sync.aligned.m8n8.x4.shared.b16 {%0,%1,%2,%3}, [%4];"
                 : "=r"(r[0]), "=r"(r[1]), "=r"(r[2]), "=r"(r[3]) : "r"(addr));
}

static __device__ __forceinline__ void mma_f16(float* c, const uint32_t* a,
                                               const uint32_t* b) {
    asm volatile(
        "mma.sync.aligned.m16n8k16.row.col.f32.f16.f16.f32 "
        "{%0,%1,%2,%3}, {%4,%5,%6,%7}, {%8,%9}, {%0,%1,%2,%3};"
        : "+f"(c[0]), "+f"(c[1]), "+f"(c[2]), "+f"(c[3])
        : "r"(a[0]), "r"(a[1]), "r"(a[2]), "r"(a[3]), "r"(b[0]), "r"(b[1]));
}

static __device__ __forceinline__ uint32_t packh2(float x0, float x1) {
    __half2 hp;
    hp.x = __float2half_rn(x0);
    hp.y = __float2half_rn(x1);
    return *(uint32_t*)&hp;
}

// ---------------------------------------------------------------------------
// conv (W_enc): fp32 -> single fp16 plane, pre-swizzled.
// ---------------------------------------------------------------------------
__global__ void conv_f16_kernel(const float* __restrict__ S, unsigned char* __restrict__ D) {
    const int gid = blockIdx.x * 256 + threadIdx.x;
    const int n   = gid >> 8;
    const int k0  = (gid & 255) << 3;
    const float* src = S + (size_t)n * OBS_DIM + k0;
    float4 v0 = *(const float4*)src;
    float4 v1 = *(const float4*)(src + 4);

    uint32_t hv[4];
    hv[0] = packh2(v0.x, v0.y);
    hv[1] = packh2(v0.z, v0.w);
    hv[2] = packh2(v1.x, v1.y);
    hv[3] = packh2(v1.z, v1.w);

    const int c  = k0 >> 6;
    const int kl = k0 & 63;
    const int t  = n >> 7;
    const int nl = n & 127;
    const uint32_t byte = (uint32_t)nl * 128 +
                          (((uint32_t)kl * 2) ^ ((uint32_t)(nl & 7) << 4));
    unsigned char* blk = D + ((size_t)(t * NCHUNK + c)) * 16384;
    *(uint4*)(blk + byte) = make_uint4(hv[0], hv[1], hv[2], hv[3]);
}

// ---------------------------------------------------------------------------
// conv W' (head B): [Ws(32); Wc(1); 0(31)] fp32[64x512] -> single fp16,
// pre-swizzled 64-row x 64-col chunks: g_Whead[c][8K]. grid 16 x 256.
// ---------------------------------------------------------------------------
__global__ void conv_wh_kernel(const float* __restrict__ Ws, const float* __restrict__ Wc) {
    const int u   = blockIdx.x * 256 + threadIdx.x;   // 0..4095
    const int row = u >> 6;                            // 0..63
    const int k0  = (u & 63) << 3;                     // 0..504 step 8
    float f[8];
    if (row < 32) {
        const float4* s4 = (const float4*)(Ws + (size_t)row * HID + k0);
        *(float4*)(f) = s4[0];
        *(float4*)(f + 4) = s4[1];
    } else if (row == 32) {
        const float4* s4 = (const float4*)(Wc + k0);
        *(float4*)(f) = s4[0];
        *(float4*)(f + 4) = s4[1];
    } else {
#pragma unroll
        for (int e = 0; e < 8; e++) f[e] = 0.f;
    }
    uint32_t hv[4];
#pragma unroll
    for (int j = 0; j < 4; j++) hv[j] = packh2(f[2 * j], f[2 * j + 1]);
    const int c  = k0 >> 6;
    const int kl = k0 & 63;
    const uint32_t byte = (uint32_t)row * 128 +
                          (((uint32_t)kl * 2) ^ ((uint32_t)(row & 7) << 4));
    *(uint4*)(g_Whead + (size_t)c * 8192 + byte) = make_uint4(hv[0], hv[1], hv[2], hv[3]);
}

// ---------------------------------------------------------------------------
// HMMA GEMM, 1-term fp16, fused x conversion (R11/R12-proven):
//   relu(x @ W_enc^T + b_enc) -> g_Ahead (single fp16 plane head tiles)
// ---------------------------------------------------------------------------
__global__ __launch_bounds__(512, 1) void enc_gemm_mma(
    const float* __restrict__ X, const float* __restrict__ bias)
{
    extern __shared__ __align__(1024) unsigned char smem[];
    const int tid = threadIdx.x;
    const int w = tid >> 5, l = tid & 31;
    const int mtile = blockIdx.x >> 1;
    const int ntile = blockIdx.x & 1;
    const int m0 = mtile * BM;
    const int n0 = ntile * BN;
    const uint32_t sb = smem_addr_u32(smem);
    float* bsm = (float*)(smem + BIAS_OFF);
    if (tid < 256) bsm[tid] = bias[n0 + tid];

    const float* gX = X + (size_t)m0 * OBS_DIM;
    const unsigned char* gB0 = g_Bstage + (size_t)(ntile * 2) * NCHUNK * 16384;
    const unsigned char* gB1 = g_Bstage + (size_t)(ntile * 2 + 1) * NCHUNK * 16384;

    float acc[4][4][4];
#pragma unroll
    for (int i = 0; i < 4; i++)
#pragma unroll
        for (int j = 0; j < 4; j++)
#pragma unroll
            for (int q = 0; q < 4; q++) acc[i][j][q] = 0.f;

    const int wm = (w >> 3) * 64;
    const int wn = (w & 7) * 32;
    const int idx = l & 7, seg = l >> 3;
    const int arl = idx + (seg & 1) * 8;
    const int acb = (seg >> 1) * 16;
    const int brl = idx + (seg >> 1) * 8;
    const int bkb = (seg & 1) * 16;
    const uint32_t sxor = (uint32_t)idx << 4;

#define ISSUE(c, slot3)                                                         \
    {                                                                           \
        const uint32_t dstA = sb + A32_OFF + (slot3) * 32768;                   \
        const uint32_t dstB = sb + B_OFF + (slot3) * 32768;                     \
        const unsigned char* gb0 = gB0 + (size_t)(c) * 16384;                   \
        const unsigned char* gb1 = gB1 + (size_t)(c) * 16384;                   \
        _Pragma("unroll") for (int i = 0; i < 4; i++) {                         \
            const int blk = i * 512 + tid;                                      \
            const float* gsrc = gX + (size_t)(blk >> 4) * OBS_DIM +             \
                                (c) * KC + (blk & 15) * 4;                      \
            asm volatile("cp.async.cg.shared.global [%0], [%1], 16;"            \
                         :: "r"(dstA + (uint32_t)blk * 16), "l"(gsrc) : "memory"); \
        }                                                                       \
        _Pragma("unroll") for (int i = 0; i < 2; i++) {                         \
            uint32_t off = (uint32_t)(i * 512 + tid) * 16;                      \
            asm volatile("cp.async.cg.shared.global [%0], [%1], 16;"            \
                         :: "r"(dstB + off), "l"(gb0 + off) : "memory");        \
            asm volatile("cp.async.cg.shared.global [%0], [%1], 16;"            \
                         :: "r"(dstB + 16384 + off), "l"(gb1 + off) : "memory"); \
        }                                                                       \
        asm volatile("cp.async.commit_group;" ::: "memory");                    \
    }

#define CONVERT(c)                                                              \
    {                                                                           \
        const int s3 = (c) % 3;                                                 \
        const int s2 = (c) & 1;                                                 \
        const unsigned char* a32 = smem + A32_OFF + s3 * 32768;                 \
        unsigned char* a16 = smem + A16_OFF + s2 * 16384;                       \
        _Pragma("unroll") for (int i = 0; i < 4; i++) {                         \
            const int blk = i * 512 + tid;                                      \
            float4 v = *(const float4*)(a32 + (size_t)blk * 16);                \
            uint32_t h0 = packh2(v.x, v.y);                                     \
            uint32_t h1 = packh2(v.z, v.w);                                     \
            const int row = blk >> 4;                                           \
            const uint32_t kb = (uint32_t)(blk & 15) * 8;                       \
            const uint32_t swo = (uint32_t)row * 128 +                          \
                                 (kb ^ ((uint32_t)(row & 7) << 4));             \
            *(uint2*)(a16 + swo) = make_uint2(h0, h1);                          \
        }                                                                       \
    }

    ISSUE(0, 0);
    ISSUE(1, 1);
    asm volatile("cp.async.wait_group 1;" ::: "memory");
    CONVERT(0);

    for (int c = 0; c < NCHUNK; c++) {
        __syncthreads();

        if (c + 2 < NCHUNK) {
            const int s3 = (c + 2) % 3;
            ISSUE(c + 2, s3);
        }

        const uint32_t stA = sb + A16_OFF + (c & 1) * 16384;
        const uint32_t stB = sb + B_OFF + (c % 3) * 32768;

#pragma unroll
        for (int ks = 0; ks < 4; ks++) {
            const int kb = ks * 32;
            uint32_t a[4][4], b[8];
#pragma unroll
            for (int mt = 0; mt < 4; mt++) {
                uint32_t off = (uint32_t)(wm + mt * 16 + arl) * 128 +
                               (((uint32_t)(kb + acb)) ^ sxor);
                ldm_x4(a[mt], stA + off);
            }
#pragma unroll
            for (int g = 0; g < 2; g++) {
                uint32_t off = (uint32_t)(wn + g * 16 + brl) * 128 +
                               (((uint32_t)(kb + bkb)) ^ sxor);
                ldm_x4(&b[g * 4], stB + off);
            }
#pragma unroll
            for (int mt = 0; mt < 4; mt++)
#pragma unroll
                for (int nt = 0; nt < 4; nt++)
                    mma_f16(acc[mt][nt], a[mt], &b[nt * 2]);
        }

        if (c + 1 < NCHUNK) {
            if (c + 2 < NCHUNK) {
                asm volatile("cp.async.wait_group 1;" ::: "memory");
            } else {
                asm volatile("cp.async.wait_group 0;" ::: "memory");
            }
            CONVERT(c + 1);
        }
    }

    // epilogue: bias + relu, write single fp16 plane head tiles
    unsigned char* gAh = g_Ahead + (size_t)mtile * 8 * 16384;
#pragma unroll
    for (int mt = 0; mt < 4; mt++)
#pragma unroll
        for (int nt = 0; nt < 4; nt++) {
            const int colL = wn + nt * 8 + (l & 3) * 2;
            const float b0 = bsm[colL], b1 = bsm[colL + 1];
            const int rloc = wm + mt * 16 + (l >> 2);
            const int n = n0 + colL;
            const int cch = n >> 6;
            const int kc = n & 63;
            unsigned char* blk = gAh + (size_t)cch * 16384;

            const uint32_t h01 = packh2(fmaxf(acc[mt][nt][0] + b0, 0.f),
                                        fmaxf(acc[mt][nt][1] + b1, 0.f));
            const uint32_t h23 = packh2(fmaxf(acc[mt][nt][2] + b0, 0.f),
                                        fmaxf(acc[mt][nt][3] + b1, 0.f));

            const uint32_t by0 = (uint32_t)rloc * 128 +
                                 (((uint32_t)(2 * kc)) ^ ((uint32_t)(rloc & 7) << 4));
            const int r1 = rloc + 8;
            const uint32_t by1 = (uint32_t)r1 * 128 +
                                 (((uint32_t)(2 * kc)) ^ ((uint32_t)(r1 & 7) << 4));
            *(uint32_t*)(blk + by0) = h01;
            *(uint32_t*)(blk + by1) = h23;
        }
}

// ---------------------------------------------------------------------------
// Head v3 (ring fixed to 4-deep): grid 256 = (mtile, mhalf). Per CTA:
// [64 x 64 x 512] 1-term fp16, A = fp16 hidden half-tiles (4-deep 8KB ring),
// B = W' fp16 (64KB, one shot). 256 threads, 2 CTAs/SM.
// smem: W' 8 x 8K @0 ; A ring 4 x 8K @65536 ; logits reuse @0.
// ---------------------------------------------------------------------------
#define HB_OFF 0
#define HA_OFF 65536
#define HEAD_SMEM 98304

__global__ __launch_bounds__(256, 2) void head_gemm_kernel(
    const float* __restrict__ bs, const float* __restrict__ bc,
    const int* __restrict__ skill, const int* __restrict__ action,
    float* __restrict__ out)
{
    extern __shared__ __align__(1024) unsigned char smem[];
    const int tid = threadIdx.x;
    const int w = tid >> 5, l = tid & 31;
    const int mtile = blockIdx.x >> 1;
    const int mhalf = blockIdx.x & 1;
    const uint32_t sb = smem_addr_u32(smem);

    // A half-tiles: rows [mhalf*64, mhalf*64+64) of each 16KB chunk
    const unsigned char* gA = g_Ahead + (size_t)mtile * 8 * 16384 + mhalf * 8192;

    // group 0: whole W' (64KB), 16 x 16B per thread
    {
        const uint32_t dst = sb + HB_OFF;
#pragma unroll
        for (int i = 0; i < 16; i++) {
            uint32_t off = (uint32_t)(i * 256 + tid) * 16;
            asm volatile("cp.async.cg.shared.global [%0], [%1], 16;"
                         :: "r"(dst + off), "l"(g_Whead + off) : "memory");
        }
        asm volatile("cp.async.commit_group;" ::: "memory");
    }

#define HISSUE(c)                                                              \
    {                                                                          \
        const uint32_t dst = sb + HA_OFF + ((c) & 3) * 8192;                   \
        const unsigned char* ga = gA + (size_t)(c) * 16384;                    \
        _Pragma("unroll") for (int i = 0; i < 2; i++) {                        \
            uint32_t off = (uint32_t)(i * 256 + tid) * 16;                     \
            asm volatile("cp.async.cg.shared.global [%0], [%1], 16;"           \
                         :: "r"(dst + off), "l"(ga + off) : "memory");         \
        }                                                                      \
        asm volatile("cp.async.commit_group;" ::: "memory");                   \
    }

    HISSUE(0);
    HISSUE(1);
    HISSUE(2);

    float acc[2][2][4];
#pragma unroll
    for (int i = 0; i < 2; i++)
#pragma unroll
        for (int j = 0; j < 2; j++)
#pragma unroll
            for (int q = 0; q < 4; q++) acc[i][j][q] = 0.f;

    const int wm = (w >> 2) * 32;    // 2 m-groups of 32 rows
    const int wn = (w & 3) * 16;     // 4 n-groups of 16 cols
    const int idx = l & 7, seg = l >> 3;
    const int arl = idx + (seg & 1) * 8;
    const int acb = (seg >> 1) * 16;
    const int brl = idx + (seg >> 1) * 8;
    const int bkb = (seg & 1) * 16;
    const uint32_t sxor = (uint32_t)idx << 4;

    for (int c = 0; c < 8; c++) {
        if (c <= 5) {
            asm volatile("cp.async.wait_group 2;" ::: "memory");
        } else if (c == 6) {
            asm volatile("cp.async.wait_group 1;" ::: "memory");
        } else {
            asm volatile("cp.async.wait_group 0;" ::: "memory");
        }
        __syncthreads();   // chunk c visible; slot (c-1)&3 retired by all warps

        if (c + 3 < 8) HISSUE(c + 3);   // writes slot (c-1)&3 — free

        const uint32_t stA = sb + HA_OFF + (c & 3) * 8192;
        const uint32_t stB = sb + HB_OFF + c * 8192;

#pragma unroll
        for (int ks = 0; ks < 4; ks++) {
            const int kb = ks * 32;
            uint32_t a[2][4], b[4];
#pragma unroll
            for (int mt = 0; mt < 2; mt++) {
                uint32_t off = (uint32_t)(wm + mt * 16 + arl) * 128 +
                               (((uint32_t)(kb + acb)) ^ sxor);
                ldm_x4(a[mt], stA + off);
            }
            {
                uint32_t off = (uint32_t)(wn + brl) * 128 +
                               (((uint32_t)(kb + bkb)) ^ sxor);
                ldm_x4(b, stB + off);
            }
#pragma unroll
            for (int mt = 0; mt < 2; mt++)
#pragma unroll
                for (int nt = 0; nt < 2; nt++)
                    mma_f16(acc[mt][nt], a[mt], &b[nt * 2]);
        }
    }

    __syncthreads();   // all MMAs done before logits overwrite W' region

    float* Lsm = (float*)(smem + HB_OFF);    // [64][66]
#pragma unroll
    for (int mt = 0; mt < 2; mt++)
#pragma unroll
        for (int nt = 0; nt < 2; nt++) {
            const int colL = wn + nt * 8 + (l & 3) * 2;
            const int r0 = wm + mt * 16 + (l >> 2);
            *(float2*)(Lsm + r0 * 66 + colL)       = make_float2(acc[mt][nt][0], acc[mt][nt][1]);
            *(float2*)(Lsm + (r0 + 8) * 66 + colL) = make_float2(acc[mt][nt][2], acc[mt][nt][3]);
        }
    __syncthreads();

    if (tid < 64) {
        const int agent = mtile * 128 + mhalf * 64 + tid;
        const float* Lr = Lsm + tid * 66;

        float lg[32];
        float mx = -1e30f;
#pragma unroll
        for (int t = 0; t < 32; t++) {
            lg[t] = Lr[t] + bs[t];
            mx = fmaxf(mx, lg[t]);
        }
        float se = 0.f, s1 = 0.f;
#pragma unroll
        for (int t = 0; t < 32; t++) {
            float e = expf(lg[t] - mx);
            se += e;
            s1 += e * lg[t];
        }
        const float lse = mx + logf(se);
        const int act = action[agent];
        const float slp = lg[act & 31] - lse;
        const float ent = lse - s1 / se;
        const float val = Lr[32] + bc[0];

        out[0 * N_AGENTS + agent] = (float)act;
        out[1 * N_AGENTS + agent] = (float)skill[agent];
        out[2 * N_AGENTS + agent] = -2.7725887222397811f;   // -ln(16)
        out[3 * N_AGENTS + agent] = slp;
        out[4 * N_AGENTS + agent] = ent;
        out[5 * N_AGENTS + agent] = val;
    }
}

// ---------------------------------------------------------------------------
// launch
// ---------------------------------------------------------------------------
extern "C" void kernel_launch(void* const* d_in, const int* in_sizes, int n_in,
                              void* d_out, int out_size) {
    (void)in_sizes; (void)n_in; (void)out_size;
    const float* x     = (const float*)d_in[0];
    const float* W_enc = (const float*)d_in[1];
    const float* b_enc = (const float*)d_in[2];
    // d_in[3]=Wm, d_in[4]=bm : dead (selections never returned)
    const float* Ws    = (const float*)d_in[5];
    const float* bs    = (const float*)d_in[6];
    const float* Wc    = (const float*)d_in[7];
    const float* bc    = (const float*)d_in[8];
    const int*   skill = (const int*)d_in[9];
    const int*   act   = (const int*)d_in[10];
    float* out = (float*)d_out;

    unsigned char* dB;
    cudaGetSymbolAddress((void**)&dB, g_Bstage);

    static int cfg_done = 0;
    if (!cfg_done) {
        cudaFuncSetAttribute(enc_gemm_mma, cudaFuncAttributeMaxDynamicSharedMemorySize,
                             SMEM_TOTAL);
        cudaFuncSetAttribute(head_gemm_kernel, cudaFuncAttributeMaxDynamicSharedMemorySize,
                             HEAD_SMEM);
        cfg_done = 1;
    }

    conv_f16_kernel<<<512, 256>>>(W_enc, dB);   // W_enc -> fp16 tiles
    conv_wh_kernel<<<16, 256>>>(Ws, Wc);        // W' -> single fp16 staging

    enc_gemm_mma<<<NTILES * MTILES, 512, SMEM_TOTAL>>>(x, b_enc);

    head_gemm_kernel<<<2 * MTILES, 256, HEAD_SMEM>>>(bs, bc, skill, act, out);
}

// round 16
// speedup vs baseline: 7.4668x; 1.0611x over previous
#include <cuda_runtime.h>
#include <cuda_bf16.h>
#include <cuda_fp16.h>
#include <stdint.h>

#define N_AGENTS 16384
#define OBS_DIM  2048
#define HID      512

// ---- enc GEMM tiling: BM=64, BN=256, KC=64, 256 threads, occ 2,
//      1-term fp16 with fused in-smem fp32->fp16 conversion of x ----
#define KC 64
#define NCHUNK (OBS_DIM / KC)    // 32
#define MT64  (N_AGENTS / 64)    // 256 m-tiles of 64 rows
#define MTILES (N_AGENTS / 128)  // 128 head tiles

// enc smem (bytes): A32 2x16K @0 ; A16 2x8K @32768 ; B 2x32K @49152 ; bias @114688
#define A32_OFF 0
#define A16_OFF 32768
#define EB_OFF  49152
#define EBIAS_OFF 114688
#define ENC_SMEM 115712

// B: pre-converted single fp16, [tile128][chunk][16K]
__device__ __align__(1024) unsigned char g_Bstage[(size_t)4 * NCHUNK * 16384];
// hidden: single fp16 plane head tiles: [mtile128][hchunk 0..7][16K]
__device__ __align__(1024) unsigned char g_Ahead[(size_t)MTILES * 8 * 16384];
// W' = [Ws(32); Wc(1); 0(31)] single fp16: [chunk 0..7][8K]
__device__ __align__(1024) unsigned char g_Whead[(size_t)8 * 8192];

static __device__ __forceinline__ uint32_t smem_addr_u32(const void* p) {
    uint32_t a;
    asm("{ .reg .u64 t; cvta.to.shared.u64 t, %1; cvt.u32.u64 %0, t; }" : "=r"(a) : "l"(p));
    return a;
}

static __device__ __forceinline__ void ldm_x4(uint32_t* r, uint32_t addr) {
    asm volatile("ldmatrix.sync.aligned.m8n8.x4.shared.b16 {%0,%1,%2,%3}, [%4];"
                 : "=r"(r[0]), "=r"(r[1]), "=r"(r[2]), "=r"(r[3]) : "r"(addr));
}

static __device__ __forceinline__ void mma_f16(float* c, const uint32_t* a,
                                               const uint32_t* b) {
    asm volatile(
        "mma.sync.aligned.m16n8k16.row.col.f32.f16.f16.f32 "
        "{%0,%1,%2,%3}, {%4,%5,%6,%7}, {%8,%9}, {%0,%1,%2,%3};"
        : "+f"(c[0]), "+f"(c[1]), "+f"(c[2]), "+f"(c[3])
        : "r"(a[0]), "r"(a[1]), "r"(a[2]), "r"(a[3]), "r"(b[0]), "r"(b[1]));
}

static __device__ __forceinline__ uint32_t packh2(float x0, float x1) {
    __half2 hp;
    hp.x = __float2half_rn(x0);
    hp.y = __float2half_rn(x1);
    return *(uint32_t*)&hp;
}

// ---------------------------------------------------------------------------
// conv (W_enc): fp32 -> single fp16 plane, pre-swizzled. (R14-proven)
// ---------------------------------------------------------------------------
__global__ void conv_f16_kernel(const float* __restrict__ S, unsigned char* __restrict__ D) {
    const int gid = blockIdx.x * 256 + threadIdx.x;
    const int n   = gid >> 8;
    const int k0  = (gid & 255) << 3;
    const float* src = S + (size_t)n * OBS_DIM + k0;
    float4 v0 = *(const float4*)src;
    float4 v1 = *(const float4*)(src + 4);

    uint32_t hv[4];
    hv[0] = packh2(v0.x, v0.y);
    hv[1] = packh2(v0.z, v0.w);
    hv[2] = packh2(v1.x, v1.y);
    hv[3] = packh2(v1.z, v1.w);

    const int c  = k0 >> 6;
    const int kl = k0 & 63;
    const int t  = n >> 7;
    const int nl = n & 127;
    const uint32_t byte = (uint32_t)nl * 128 +
                          (((uint32_t)kl * 2) ^ ((uint32_t)(nl & 7) << 4));
    unsigned char* blk = D + ((size_t)(t * NCHUNK + c)) * 16384;
    *(uint4*)(blk + byte) = make_uint4(hv[0], hv[1], hv[2], hv[3]);
}

// ---------------------------------------------------------------------------
// conv W' (head B): [Ws(32); Wc(1); 0(31)] -> single fp16 chunks (R14-proven)
// ---------------------------------------------------------------------------
__global__ void conv_wh_kernel(const float* __restrict__ Ws, const float* __restrict__ Wc) {
    const int u   = blockIdx.x * 256 + threadIdx.x;   // 0..4095
    const int row = u >> 6;
    const int k0  = (u & 63) << 3;
    float f[8];
    if (row < 32) {
        const float4* s4 = (const float4*)(Ws + (size_t)row * HID + k0);
        *(float4*)(f) = s4[0];
        *(float4*)(f + 4) = s4[1];
    } else if (row == 32) {
        const float4* s4 = (const float4*)(Wc + k0);
        *(float4*)(f) = s4[0];
        *(float4*)(f + 4) = s4[1];
    } else {
#pragma unroll
        for (int e = 0; e < 8; e++) f[e] = 0.f;
    }
    uint32_t hv[4];
#pragma unroll
    for (int j = 0; j < 4; j++) hv[j] = packh2(f[2 * j], f[2 * j + 1]);
    const int c  = k0 >> 6;
    const int kl = k0 & 63;
    const uint32_t byte = (uint32_t)row * 128 +
                          (((uint32_t)kl * 2) ^ ((uint32_t)(row & 7) << 4));
    *(uint4*)(g_Whead + (size_t)c * 8192 + byte) = make_uint4(hv[0], hv[1], hv[2], hv[3]);
}

// ---------------------------------------------------------------------------
// enc GEMM v2 (prologue race FIXED): BM=64, occ 2.
// relu(x @ W_enc^T + b_enc) -> g_Ahead fp16 tiles.
// Prologue: G0={A0,A1,B0}; wait 0; convert(0); G1={A2,B1}.
// Loop c: wait(<=1)[endof(c-2) done] | sync | compute(c) | convert(c+1) |
//         sync | issue{A(c+3), B(c+2)}.
// ---------------------------------------------------------------------------
__global__ __launch_bounds__(256, 2) void enc_gemm_mma(
    const float* __restrict__ X, const float* __restrict__ bias)
{
    extern __shared__ __align__(1024) unsigned char smem[];
    const int tid = threadIdx.x;
    const int w = tid >> 5, l = tid & 31;
    const int mt64  = blockIdx.x >> 1;
    const int ntile = blockIdx.x & 1;
    const int m0 = mt64 * 64;
    const int n0 = ntile * 256;
    const uint32_t sb = smem_addr_u32(smem);
    float* bsm = (float*)(smem + EBIAS_OFF);
    bsm[tid] = bias[n0 + tid];

    const float* gX = X + (size_t)m0 * OBS_DIM;
    const unsigned char* gB0 = g_Bstage + (size_t)(ntile * 2) * NCHUNK * 16384;
    const unsigned char* gB1 = g_Bstage + (size_t)(ntile * 2 + 1) * NCHUNK * 16384;

    float acc[4][4][4];
#pragma unroll
    for (int i = 0; i < 4; i++)
#pragma unroll
        for (int j = 0; j < 4; j++)
#pragma unroll
            for (int q = 0; q < 4; q++) acc[i][j][q] = 0.f;

    const int wn = w * 32;               // 8 warps x 32 cols; all warps span 64 rows
    const int idx = l & 7, seg = l >> 3;
    const int arl = idx + (seg & 1) * 8;
    const int acb = (seg >> 1) * 16;
    const int brl = idx + (seg >> 1) * 8;
    const int bkb = (seg & 1) * 16;
    const uint32_t sxor = (uint32_t)idx << 4;

#define EISSUE_A(k)                                                             \
    {                                                                           \
        const uint32_t dstA = sb + A32_OFF + ((k) & 1) * 16384;                 \
        _Pragma("unroll") for (int i = 0; i < 4; i++) {                         \
            const int blk = i * 256 + tid;                                      \
            const float* gsrc = gX + (size_t)(blk >> 4) * OBS_DIM +             \
                                (k) * KC + (blk & 15) * 4;                      \
            asm volatile("cp.async.cg.shared.global [%0], [%1], 16;"            \
                         :: "r"(dstA + (uint32_t)blk * 16), "l"(gsrc) : "memory"); \
        }                                                                       \
    }

#define EISSUE_B(k)                                                             \
    {                                                                           \
        const uint32_t dstB = sb + EB_OFF + ((k) & 1) * 32768;                  \
        const unsigned char* gb0 = gB0 + (size_t)(k) * 16384;                   \
        const unsigned char* gb1 = gB1 + (size_t)(k) * 16384;                   \
        _Pragma("unroll") for (int i = 0; i < 4; i++) {                         \
            uint32_t off = (uint32_t)(i * 256 + tid) * 16;                      \
            asm volatile("cp.async.cg.shared.global [%0], [%1], 16;"            \
                         :: "r"(dstB + off), "l"(gb0 + off) : "memory");        \
            asm volatile("cp.async.cg.shared.global [%0], [%1], 16;"            \
                         :: "r"(dstB + 16384 + off), "l"(gb1 + off) : "memory"); \
        }                                                                       \
    }

#define ECOMMIT() asm volatile("cp.async.commit_group;" ::: "memory")

#define ECONVERT(k)                                                             \
    {                                                                           \
        const unsigned char* a32 = smem + A32_OFF + ((k) & 1) * 16384;          \
        unsigned char* a16 = smem + A16_OFF + ((k) & 1) * 8192;                 \
        _Pragma("unroll") for (int i = 0; i < 4; i++) {                         \
            const int blk = i * 256 + tid;                                      \
            float4 v = *(const float4*)(a32 + (size_t)blk * 16);                \
            uint32_t h0 = packh2(v.x, v.y);                                     \
            uint32_t h1 = packh2(v.z, v.w);                                     \
            const int row = blk >> 4;                                           \
            const uint32_t kb = (uint32_t)(blk & 15) * 8;                       \
            const uint32_t swo = (uint32_t)row * 128 +                          \
                                 (kb ^ ((uint32_t)(row & 7) << 4));             \
            *(uint2*)(a16 + swo) = make_uint2(h0, h1);                          \
        }                                                                       \
    }

    // prologue (FIXED): convert(0) must finish reading A32 slot 0 before
    // A(2) (which aliases slot 0 in the 2-deep ring) is issued.
    EISSUE_A(0); EISSUE_A(1); EISSUE_B(0); ECOMMIT();   // G0
    asm volatile("cp.async.wait_group 0;" ::: "memory"); // G0 done
    ECONVERT(0);                                         // slot 0 safe
    EISSUE_A(2); EISSUE_B(1); ECOMMIT();                 // G1 (A2 -> slot 0)

    for (int c = 0; c < NCHUNK; c++) {
        // drain endof(c-2) = {A32(c+1), B(c)}; leave endof(c-1) in flight
        if (c < NCHUNK - 1) {
            asm volatile("cp.async.wait_group 1;" ::: "memory");
        } else {
            asm volatile("cp.async.wait_group 0;" ::: "memory");
        }
        __syncthreads();   // A16(c), B(c) visible to all

        const uint32_t stA = sb + A16_OFF + (c & 1) * 8192;
        const uint32_t stB = sb + EB_OFF + (c & 1) * 32768;

#pragma unroll
        for (int ks = 0; ks < 4; ks++) {
            const int kb = ks * 32;
            uint32_t a[4][4], b[8];
#pragma unroll
            for (int mt = 0; mt < 4; mt++) {
                uint32_t off = (uint32_t)(mt * 16 + arl) * 128 +
                               (((uint32_t)(kb + acb)) ^ sxor);
                ldm_x4(a[mt], stA + off);
            }
#pragma unroll
            for (int g = 0; g < 2; g++) {
                uint32_t off = (uint32_t)(wn + g * 16 + brl) * 128 +
                               (((uint32_t)(kb + bkb)) ^ sxor);
                ldm_x4(&b[g * 4], stB + off);
            }
#pragma unroll
            for (int mt = 0; mt < 4; mt++)
#pragma unroll
                for (int nt = 0; nt < 4; nt++)
                    mma_f16(acc[mt][nt], a[mt], &b[nt * 2]);
        }

        if (c + 1 < NCHUNK) ECONVERT(c + 1);   // A32(c+1) drained at top wait

        __syncthreads();   // converts + compute reads done before slot reuse

        const bool iA = (c + 3 < NCHUNK);
        const bool iB = (c + 2 < NCHUNK);
        if (iA) EISSUE_A(c + 3);   // slot (c+1)&1: convert(c+1) just finished
        if (iB) EISSUE_B(c + 2);   // slot c&1: compute(c) just finished
        if (iA || iB) ECOMMIT();
    }

    // epilogue: bias + relu, write single fp16 plane head tiles
    unsigned char* gAh = g_Ahead + (size_t)(mt64 >> 1) * 8 * 16384;
    const int rbase = (mt64 & 1) * 64;
#pragma unroll
    for (int mt = 0; mt < 4; mt++)
#pragma unroll
        for (int nt = 0; nt < 4; nt++) {
            const int colL = wn + nt * 8 + (l & 3) * 2;
            const float b0 = bsm[colL], b1 = bsm[colL + 1];
            const int r0 = rbase + mt * 16 + (l >> 2);
            const int n = n0 + colL;
            const int cch = n >> 6;
            const int kc = n & 63;
            unsigned char* blk = gAh + (size_t)cch * 16384;

            const uint32_t h01 = packh2(fmaxf(acc[mt][nt][0] + b0, 0.f),
                                        fmaxf(acc[mt][nt][1] + b1, 0.f));
            const uint32_t h23 = packh2(fmaxf(acc[mt][nt][2] + b0, 0.f),
                                        fmaxf(acc[mt][nt][3] + b1, 0.f));

            const uint32_t by0 = (uint32_t)r0 * 128 +
                                 (((uint32_t)(2 * kc)) ^ ((uint32_t)(r0 & 7) << 4));
            const int r1 = r0 + 8;
            const uint32_t by1 = (uint32_t)r1 * 128 +
                                 (((uint32_t)(2 * kc)) ^ ((uint32_t)(r1 & 7) << 4));
            *(uint32_t*)(blk + by0) = h01;
            *(uint32_t*)(blk + by1) = h23;
        }
}

// ---------------------------------------------------------------------------
// Head v3 (R14-proven): grid 256 = (mtile, mhalf), [64 x 64 x 512] 1-term fp16,
// A ring 4-deep, W' one-shot, 2 CTAs/SM; per-agent softmax/entropy/value.
// ---------------------------------------------------------------------------
#define HB_OFF 0
#define HA_OFF 65536
#define HEAD_SMEM 98304

__global__ __launch_bounds__(256, 2) void head_gemm_kernel(
    const float* __restrict__ bs, const float* __restrict__ bc,
    const int* __restrict__ skill, const int* __restrict__ action,
    float* __restrict__ out)
{
    extern __shared__ __align__(1024) unsigned char smem[];
    const int tid = threadIdx.x;
    const int w = tid >> 5, l = tid & 31;
    const int mtile = blockIdx.x >> 1;
    const int mhalf = blockIdx.x & 1;
    const uint32_t sb = smem_addr_u32(smem);

    const unsigned char* gA = g_Ahead + (size_t)mtile * 8 * 16384 + mhalf * 8192;

    {
        const uint32_t dst = sb + HB_OFF;
#pragma unroll
        for (int i = 0; i < 16; i++) {
            uint32_t off = (uint32_t)(i * 256 + tid) * 16;
            asm volatile("cp.async.cg.shared.global [%0], [%1], 16;"
                         :: "r"(dst + off), "l"(g_Whead + off) : "memory");
        }
        asm volatile("cp.async.commit_group;" ::: "memory");
    }

#define HISSUE(c)                                                              \
    {                                                                          \
        const uint32_t dst = sb + HA_OFF + ((c) & 3) * 8192;                   \
        const unsigned char* ga = gA + (size_t)(c) * 16384;                    \
        _Pragma("unroll") for (int i = 0; i < 2; i++) {                        \
            uint32_t off = (uint32_t)(i * 256 + tid) * 16;                     \
            asm volatile("cp.async.cg.shared.global [%0], [%1], 16;"           \
                         :: "r"(dst + off), "l"(ga + off) : "memory");         \
        }                                                                      \
        asm volatile("cp.async.commit_group;" ::: "memory");                   \
    }

    HISSUE(0);
    HISSUE(1);
    HISSUE(2);

    float acc[2][2][4];
#pragma unroll
    for (int i = 0; i < 2; i++)
#pragma unroll
        for (int j = 0; j < 2; j++)
#pragma unroll
            for (int q = 0; q < 4; q++) acc[i][j][q] = 0.f;

    const int wm = (w >> 2) * 32;
    const int wn = (w & 3) * 16;
    const int idx = l & 7, seg = l >> 3;
    const int arl = idx + (seg & 1) * 8;
    const int acb = (seg >> 1) * 16;
    const int brl = idx + (seg >> 1) * 8;
    const int bkb = (seg & 1) * 16;
    const uint32_t sxor = (uint32_t)idx << 4;

    for (int c = 0; c < 8; c++) {
        if (c <= 5) {
            asm volatile("cp.async.wait_group 2;" ::: "memory");
        } else if (c == 6) {
            asm volatile("cp.async.wait_group 1;" ::: "memory");
        } else {
            asm volatile("cp.async.wait_group 0;" ::: "memory");
        }
        __syncthreads();

        if (c + 3 < 8) HISSUE(c + 3);

        const uint32_t stA = sb + HA_OFF + (c & 3) * 8192;
        const uint32_t stB = sb + HB_OFF + c * 8192;

#pragma unroll
        for (int ks = 0; ks < 4; ks++) {
            const int kb = ks * 32;
            uint32_t a[2][4], b[4];
#pragma unroll
            for (int mt = 0; mt < 2; mt++) {
                uint32_t off = (uint32_t)(wm + mt * 16 + arl) * 128 +
                               (((uint32_t)(kb + acb)) ^ sxor);
                ldm_x4(a[mt], stA + off);
            }
            {
                uint32_t off = (uint32_t)(wn + brl) * 128 +
                               (((uint32_t)(kb + bkb)) ^ sxor);
                ldm_x4(b, stB + off);
            }
#pragma unroll
            for (int mt = 0; mt < 2; mt++)
#pragma unroll
                for (int nt = 0; nt < 2; nt++)
                    mma_f16(acc[mt][nt], a[mt], &b[nt * 2]);
        }
    }

    __syncthreads();

    float* Lsm = (float*)(smem + HB_OFF);    // [64][66]
#pragma unroll
    for (int mt = 0; mt < 2; mt++)
#pragma unroll
        for (int nt = 0; nt < 2; nt++) {
            const int colL = wn + nt * 8 + (l & 3) * 2;
            const int r0 = wm + mt * 16 + (l >> 2);
            *(float2*)(Lsm + r0 * 66 + colL)       = make_float2(acc[mt][nt][0], acc[mt][nt][1]);
            *(float2*)(Lsm + (r0 + 8) * 66 + colL) = make_float2(acc[mt][nt][2], acc[mt][nt][3]);
        }
    __syncthreads();

    if (tid < 64) {
        const int agent = mtile * 128 + mhalf * 64 + tid;
        const float* Lr = Lsm + tid * 66;

        float lg[32];
        float mx = -1e30f;
#pragma unroll
        for (int t = 0; t < 32; t++) {
            lg[t] = Lr[t] + bs[t];
            mx = fmaxf(mx, lg[t]);
        }
        float se = 0.f, s1 = 0.f;
#pragma unroll
        for (int t = 0; t < 32; t++) {
            float e = expf(lg[t] - mx);
            se += e;
            s1 += e * lg[t];
        }
        const float lse = mx + logf(se);
        const int act = action[agent];
        const float slp = lg[act & 31] - lse;
        const float ent = lse - s1 / se;
        const float val = Lr[32] + bc[0];

        out[0 * N_AGENTS + agent] = (float)act;
        out[1 * N_AGENTS + agent] = (float)skill[agent];
        out[2 * N_AGENTS + agent] = -2.7725887222397811f;   // -ln(16)
        out[3 * N_AGENTS + agent] = slp;
        out[4 * N_AGENTS + agent] = ent;
        out[5 * N_AGENTS + agent] = val;
    }
}

// ---------------------------------------------------------------------------
// launch
// ---------------------------------------------------------------------------
extern "C" void kernel_launch(void* const* d_in, const int* in_sizes, int n_in,
                              void* d_out, int out_size) {
    (void)in_sizes; (void)n_in; (void)out_size;
    const float* x     = (const float*)d_in[0];
    const float* W_enc = (const float*)d_in[1];
    const float* b_enc = (const float*)d_in[2];
    // d_in[3]=Wm, d_in[4]=bm : dead (selections never returned)
    const float* Ws    = (const float*)d_in[5];
    const float* bs    = (const float*)d_in[6];
    const float* Wc    = (const float*)d_in[7];
    const float* bc    = (const float*)d_in[8];
    const int*   skill = (const int*)d_in[9];
    const int*   act   = (const int*)d_in[10];
    float* out = (float*)d_out;

    unsigned char* dB;
    cudaGetSymbolAddress((void**)&dB, g_Bstage);

    static int cfg_done = 0;
    if (!cfg_done) {
        cudaFuncSetAttribute(enc_gemm_mma, cudaFuncAttributeMaxDynamicSharedMemorySize,
                             ENC_SMEM);
        cudaFuncSetAttribute(head_gemm_kernel, cudaFuncAttributeMaxDynamicSharedMemorySize,
                             HEAD_SMEM);
        cfg_done = 1;
    }

    conv_f16_kernel<<<512, 256>>>(W_enc, dB);   // W_enc -> fp16 tiles
    conv_wh_kernel<<<16, 256>>>(Ws, Wc);        // W' -> single fp16 staging

    enc_gemm_mma<<<2 * MT64, 256, ENC_SMEM>>>(x, b_enc);

    head_gemm_kernel<<<2 * MTILES, 256, HEAD_SMEM>>>(bs, bc, skill, act, out);
}